// round 12
// baseline (speedup 1.0000x reference)
#include <cuda_runtime.h>
#include <cuda_bf16.h>
#include <mma.h>
#include <math.h>

using namespace nvcuda;

#define N 16384
#define HID 256
#define MI 128
#define NEDGE (N*4)

// exp(2*dot) = exp2(acc * 2*log2(e)/(127*127)),  acc = dot*16129
#define QSC (2.8853900817779268f / 16129.0f)

// stats layout inside g_stats
#define RS1 0
#define RS2 (N)
#define PS1 (2*N)
#define PS2 (3*N)
#define SP1 (4*N)
#define SP2 (5*N)

// ---------------- scratch (device globals; no allocation allowed) ----------
__device__ float g_p1[(size_t)N*MI];
__device__ float g_p2[(size_t)N*MI];
__device__ signed char g_p1q[(size_t)N*MI];
__device__ signed char g_p2q[(size_t)N*MI];
__device__ float g_stats[6*N];

// ---------------- nop spacer (positions sim as the 4th launch for ncu) -----
__global__ void nop_kernel() {}

// ============ projection (tf32 wmma): p = l2norm(relu(h@W + b)) =============
// CTA: 16 rows x 128 cols, 128 threads = 4 warps; warp w owns col range w*32.
// First 384 blocks also zero g_stats. Emits fp32 p (positives) + int8 q (sim).
#define PJ_LD 132

__global__ void __launch_bounds__(128, 1) proj_kernel(
        const float* __restrict__ h1, const float* __restrict__ h2,
        const float* __restrict__ W, const float* __restrict__ bias) {
    __shared__ float cs[16 * PJ_LD];
    __shared__ float rowsq[16];

    int tid = threadIdx.x;
    int warp = tid >> 5;
    int row0 = blockIdx.x * 16;

    if (blockIdx.x < 384) {
        int base = blockIdx.x * 256;
        g_stats[base + tid] = 0.0f;
        g_stats[base + tid + 128] = 0.0f;
    }

    const float* hsrc;
    float* pdst;
    signed char* qdst;
    if (row0 < N) {
        hsrc = h1 + (size_t)row0 * HID;
        pdst = g_p1 + (size_t)row0 * MI;
        qdst = g_p1q + (size_t)row0 * MI;
    } else {
        int r0 = row0 - N;
        hsrc = h2 + (size_t)r0 * HID;
        pdst = g_p2 + (size_t)r0 * MI;
        qdst = g_p2q + (size_t)r0 * MI;
    }

    wmma::fragment<wmma::accumulator, 16, 16, 8, float> acc0;
    wmma::fragment<wmma::accumulator, 16, 16, 8, float> acc1;
    wmma::fill_fragment(acc0, 0.0f);
    wmma::fill_fragment(acc1, 0.0f);

    int n0 = warp * 32;
    for (int k = 0; k < HID; k += 8) {
        wmma::fragment<wmma::matrix_a, 16, 16, 8, wmma::precision::tf32,
                       wmma::row_major> af;
        wmma::load_matrix_sync(af, hsrc + k, HID);
        for (int i = 0; i < af.num_elements; i++)
            af.x[i] = wmma::__float_to_tf32(af.x[i]);

        wmma::fragment<wmma::matrix_b, 16, 16, 8, wmma::precision::tf32,
                       wmma::row_major> bf0;
        wmma::fragment<wmma::matrix_b, 16, 16, 8, wmma::precision::tf32,
                       wmma::row_major> bf1;
        wmma::load_matrix_sync(bf0, W + (size_t)k * MI + n0, MI);
        wmma::load_matrix_sync(bf1, W + (size_t)k * MI + n0 + 16, MI);
        for (int i = 0; i < bf0.num_elements; i++)
            bf0.x[i] = wmma::__float_to_tf32(bf0.x[i]);
        for (int i = 0; i < bf1.num_elements; i++)
            bf1.x[i] = wmma::__float_to_tf32(bf1.x[i]);

        wmma::mma_sync(acc0, af, bf0, acc0);
        wmma::mma_sync(acc1, af, bf1, acc1);
    }

    wmma::store_matrix_sync(cs + n0, acc0, PJ_LD, wmma::mem_row_major);
    wmma::store_matrix_sync(cs + n0 + 16, acc1, PJ_LD, wmma::mem_row_major);
    if (tid < 16) rowsq[tid] = 0.0f;
    __syncthreads();

    int r = tid >> 3;
    int c0 = (tid & 7) * 16;
    float vals[16];
    float sq = 0.0f;
    for (int c = 0; c < 16; c++) {
        float v = cs[r * PJ_LD + c0 + c] + bias[c0 + c];
        v = fmaxf(v, 0.0f);
        vals[c] = v;
        sq += v * v;
    }
    atomicAdd(&rowsq[r], sq);
    __syncthreads();

    float s = rsqrtf(rowsq[r]);
    unsigned int qw[4];
    for (int g = 0; g < 4; g++) qw[g] = 0u;
    for (int c = 0; c < 16; c++) {
        float o = vals[c] * s;
        pdst[(size_t)r * MI + c0 + c] = o;
        int q = __float2int_rn(o * 127.0f);
        qw[c >> 2] |= ((unsigned int)q & 255u) << ((c & 3) * 8);
    }
    int4 qv;
    qv.x = (int)qw[0];
    qv.y = (int)qw[1];
    qv.z = (int)qw[2];
    qv.w = (int)qw[3];
    *(int4*)(qdst + (size_t)r * MI + c0) = qv;
}

// ============ sim kernel (s8 wmma IMMA): exp(dot/T) row + col sums ==========
// CTA: 256 threads = 8 warps (4M x 2N); warp tile 32x64; 128x128 CTA tile,
// K=128 resident as int8 (halved smem wavefront traffic vs bf16 -- the
// binding resource per R9-R11 profiles). s32 accumulators; register epilogue
// (D-fragment lane mapping identical to the f32 case verified in Round 7):
//   x[e] -> row = (lane>>2) + ((e>>1)&1)*8
//           col = (lane&3)*2 + (e&1) + ((e>>2)&1)*8
#define SLD 144            // A/B smem row stride in bytes (int8 elements)
#define SIM_SMEM (2*128*SLD)   // 36864 bytes

__global__ void __launch_bounds__(256, 2) sim_kernel() {
    extern __shared__ char dynsm[];
    signed char* As = (signed char*)dynsm;
    signed char* Bs = As + 128 * SLD;
    __shared__ float rowred[128];
    __shared__ float colred[128];

    int tid = threadIdx.x;
    int warp = tid >> 5;
    int lane = tid & 31;
    int wm = warp >> 1;          // 0..3  (rows wm*32)
    int wn = warp & 1;           // 0..1  (cols wn*64)
    int i0 = blockIdx.y * 128;
    int j0 = blockIdx.x * 128;

    const uint4* srcA = (const uint4*)(g_p1q + (size_t)i0 * MI);
    const uint4* srcB = (const uint4*)(g_p2q + (size_t)j0 * MI);
    for (int idx = tid; idx < 1024; idx += 256) {
        int r = idx >> 3;
        int ch = idx & 7;
        *(uint4*)(As + r * SLD + ch * 16) = srcA[idx];
        *(uint4*)(Bs + r * SLD + ch * 16) = srcB[idx];
    }
    if (tid < 128) {
        rowred[tid] = 0.0f;
        colred[tid] = 0.0f;
    }
    __syncthreads();

    wmma::fragment<wmma::accumulator, 16, 16, 16, int> acc[2][4];
    #pragma unroll
    for (int mt = 0; mt < 2; mt++) {
        #pragma unroll
        for (int nt = 0; nt < 4; nt++)
            wmma::fill_fragment(acc[mt][nt], 0);
    }

    const signed char* abase = As + (wm * 32) * SLD;
    const signed char* bbase = Bs + (wn * 64) * SLD;

    #pragma unroll
    for (int k = 0; k < 8; k++) {
        wmma::fragment<wmma::matrix_a, 16, 16, 16, signed char,
                       wmma::row_major> af0;
        wmma::fragment<wmma::matrix_a, 16, 16, 16, signed char,
                       wmma::row_major> af1;
        wmma::load_matrix_sync(af0, abase + k * 16, SLD);
        wmma::load_matrix_sync(af1, abase + 16 * SLD + k * 16, SLD);
        #pragma unroll
        for (int nt = 0; nt < 4; nt++) {
            wmma::fragment<wmma::matrix_b, 16, 16, 16, signed char,
                           wmma::col_major> bf;
            wmma::load_matrix_sync(bf, bbase + nt * 16 * SLD + k * 16, SLD);
            wmma::mma_sync(acc[0][nt], af0, bf, acc[0][nt]);
            wmma::mma_sync(acc[1][nt], af1, bf, acc[1][nt]);
        }
    }

    // ---- register epilogue: exp + row/col sums via shuffles ----
    float cs0[4];
    float cs1[4];
    float cs2[4];
    float cs3[4];
    #pragma unroll
    for (int nt = 0; nt < 4; nt++) {
        cs0[nt] = 0.0f;
        cs1[nt] = 0.0f;
        cs2[nt] = 0.0f;
        cs3[nt] = 0.0f;
    }
    #pragma unroll
    for (int mt = 0; mt < 2; mt++) {
        float rlo = 0.0f;
        float rhi = 0.0f;
        #pragma unroll
        for (int nt = 0; nt < 4; nt++) {
            float e0 = exp2f((float)acc[mt][nt].x[0] * QSC);
            float e1 = exp2f((float)acc[mt][nt].x[1] * QSC);
            float e2 = exp2f((float)acc[mt][nt].x[2] * QSC);
            float e3 = exp2f((float)acc[mt][nt].x[3] * QSC);
            float e4 = exp2f((float)acc[mt][nt].x[4] * QSC);
            float e5 = exp2f((float)acc[mt][nt].x[5] * QSC);
            float e6 = exp2f((float)acc[mt][nt].x[6] * QSC);
            float e7 = exp2f((float)acc[mt][nt].x[7] * QSC);
            rlo += e0 + e1 + e4 + e5;     // row (lane>>2)
            rhi += e2 + e3 + e6 + e7;     // row (lane>>2)+8
            cs0[nt] += e0 + e2;           // col base
            cs1[nt] += e1 + e3;           // col base+1
            cs2[nt] += e4 + e6;           // col base+8
            cs3[nt] += e5 + e7;           // col base+9
        }
        rlo += __shfl_xor_sync(0xffffffffu, rlo, 1);
        rlo += __shfl_xor_sync(0xffffffffu, rlo, 2);
        rhi += __shfl_xor_sync(0xffffffffu, rhi, 1);
        rhi += __shfl_xor_sync(0xffffffffu, rhi, 2);
        if ((lane & 3) == 0) {
            int r = wm * 32 + mt * 16 + (lane >> 2);
            atomicAdd(&rowred[r], rlo);
            atomicAdd(&rowred[r + 8], rhi);
        }
    }
    #pragma unroll
    for (int nt = 0; nt < 4; nt++) {
        float v0 = cs0[nt];
        float v1 = cs1[nt];
        float v2 = cs2[nt];
        float v3 = cs3[nt];
        v0 += __shfl_xor_sync(0xffffffffu, v0, 4);
        v0 += __shfl_xor_sync(0xffffffffu, v0, 8);
        v0 += __shfl_xor_sync(0xffffffffu, v0, 16);
        v1 += __shfl_xor_sync(0xffffffffu, v1, 4);
        v1 += __shfl_xor_sync(0xffffffffu, v1, 8);
        v1 += __shfl_xor_sync(0xffffffffu, v1, 16);
        v2 += __shfl_xor_sync(0xffffffffu, v2, 4);
        v2 += __shfl_xor_sync(0xffffffffu, v2, 8);
        v2 += __shfl_xor_sync(0xffffffffu, v2, 16);
        v3 += __shfl_xor_sync(0xffffffffu, v3, 4);
        v3 += __shfl_xor_sync(0xffffffffu, v3, 8);
        v3 += __shfl_xor_sync(0xffffffffu, v3, 16);
        if (lane < 4) {
            int cb = wn * 64 + nt * 16 + lane * 2;
            atomicAdd(&colred[cb], v0);
            atomicAdd(&colred[cb + 1], v1);
            atomicAdd(&colred[cb + 8], v2);
            atomicAdd(&colred[cb + 9], v3);
        }
    }
    __syncthreads();

    if (tid < 128) {
        atomicAdd(&g_stats[RS1 + i0 + tid], rowred[tid]);
        atomicAdd(&g_stats[RS2 + j0 + tid], colred[tid]);
    }
}

// ---------------- positives: warp per edge, both directions (fp32) ---------
__global__ void pos_kernel(const int* __restrict__ pr, const int* __restrict__ pc) {
    int e = (blockIdx.x * blockDim.x + threadIdx.x) >> 5;
    int lane = threadIdx.x & 31;
    if (e >= NEDGE) return;
    int r = pr[e];
    int c = pc[e];
    const float4* p1r = (const float4*)(g_p1 + (size_t)r * MI);
    const float4* p2r = (const float4*)(g_p2 + (size_t)r * MI);
    const float4* p1c = (const float4*)(g_p1 + (size_t)c * MI);
    const float4* p2c = (const float4*)(g_p2 + (size_t)c * MI);
    float4 a1 = p1r[lane];
    float4 b2 = p2c[lane];
    float4 a2 = p2r[lane];
    float4 b1 = p1c[lane];
    float d1 = a1.x * b2.x + a1.y * b2.y + a1.z * b2.z + a1.w * b2.w;
    float d2 = a2.x * b1.x + a2.y * b1.y + a2.z * b1.z + a2.w * b1.w;
    for (int o = 16; o > 0; o >>= 1) {
        d1 += __shfl_down_sync(0xffffffffu, d1, o);
        d2 += __shfl_down_sync(0xffffffffu, d2, o);
    }
    if (lane == 0) {
        float s1 = 2.0f * d1;
        float s2 = 2.0f * d2;
        atomicAdd(&g_stats[SP1 + r], s1);
        atomicAdd(&g_stats[PS1 + r], __expf(s1));
        atomicAdd(&g_stats[SP2 + r], s2);
        atomicAdd(&g_stats[PS2 + r], __expf(s2));
    }
}

// ---------------- final loss reduction ----------------
// NOTE: the denominator subtracts the EXACT fp32 positive exp, while rowsum
// contains the int8-quantized version of those 4 entries; the mismatch is
// O(1e-4) relative on a 20000-scale sum -- negligible.
__global__ void loss_kernel(float* out) {
    float acc = 0.f;
    const float invcnt = 0.25f;   // exactly 4 positives per row by construction
    for (int i = threadIdx.x; i < N; i += blockDim.x) {
        float per1 = g_stats[SP1 + i] * invcnt
                   - __logf(g_stats[RS1 + i] - g_stats[PS1 + i]);
        float per2 = g_stats[SP2 + i] * invcnt
                   - __logf(g_stats[RS2 + i] - g_stats[PS2 + i]);
        acc += per1 + per2;
    }
    __shared__ float red[32];
    for (int o = 16; o > 0; o >>= 1)
        acc += __shfl_down_sync(0xffffffffu, acc, o);
    if ((threadIdx.x & 31) == 0) red[threadIdx.x >> 5] = acc;
    __syncthreads();
    if (threadIdx.x == 0) {
        float t = 0.f;
        int nw = blockDim.x >> 5;
        for (int w = 0; w < nw; w++) t += red[w];
        out[0] = -0.5f * t / (float)N;
    }
}

// ---------------- launch ----------------
extern "C" void kernel_launch(void* const* d_in, const int* in_sizes, int n_in,
                              void* d_out, int out_size) {
    const float* h1 = (const float*)d_in[0];
    const float* h2 = (const float*)d_in[1];
    const float* W  = (const float*)d_in[2];
    const float* b  = (const float*)d_in[3];
    const int*   pr = (const int*)d_in[4];
    const int*   pc = (const int*)d_in[5];
    float* out = (float*)d_out;

    proj_kernel<<<(2 * N) / 16, 128>>>(h1, h2, W, b);
    pos_kernel<<<(NEDGE * 32) / 256, 256>>>(pr, pc);
    nop_kernel<<<1, 32>>>();

    cudaFuncSetAttribute(sim_kernel,
                         cudaFuncAttributeMaxDynamicSharedMemorySize, SIM_SMEM);
    dim3 simgrid(N / 128, N / 128);
    sim_kernel<<<simgrid, 256, SIM_SMEM>>>();

    loss_kernel<<<1, 1024>>>(out);
}

// round 13
// speedup vs baseline: 1.9619x; 1.9619x over previous
#include <cuda_runtime.h>
#include <cuda_bf16.h>
#include <mma.h>
#include <math.h>

using namespace nvcuda;

#define N 16384
#define HID 256
#define MI 128
#define NEDGE (N*4)

// stats layout inside g_stats
#define RS1 0
#define RS2 (N)
#define PS1 (2*N)
#define PS2 (3*N)
#define SP1 (4*N)
#define SP2 (5*N)

// ---------------- scratch (device globals; no allocation allowed) ----------
__device__ float g_p1[(size_t)N*MI];
__device__ float g_p2[(size_t)N*MI];
__device__ __nv_bfloat16 g_p1h[(size_t)N*MI];
__device__ __nv_bfloat16 g_p2h[(size_t)N*MI];
__device__ float g_stats[6*N];

// ---------------- nop spacer (positions sim as the 4th launch for ncu) -----
__global__ void nop_kernel() {}

// ============ projection (tf32 wmma): p = l2norm(relu(h@W + b)) =============
// CTA: 64 rows (4 tiles of 16) x 128 cols, 128 threads = 4 warps; warp w owns
// col range w*32. W is re-read per row tile but stays L1-hot (32KB per warp),
// cutting L2 W traffic 4x vs 16-row CTAs. Grid 512; each block also zeroes
// 192 floats of g_stats (512*192 = 6*N).
#define PJ_LD 132

__global__ void __launch_bounds__(128, 1) proj_kernel(
        const float* __restrict__ h1, const float* __restrict__ h2,
        const float* __restrict__ W, const float* __restrict__ bias) {
    __shared__ float cs[16 * PJ_LD];
    __shared__ float rowsq[16];

    int tid = threadIdx.x;
    int warp = tid >> 5;
    int blk0 = blockIdx.x * 64;

    {
        int base = blockIdx.x * 192;
        g_stats[base + tid] = 0.0f;
        if (tid < 64) g_stats[base + 128 + tid] = 0.0f;
    }

    int n0 = warp * 32;

    for (int rt = 0; rt < 4; rt++) {
        int row0 = blk0 + rt * 16;
        const float* hsrc;
        float* pdst;
        __nv_bfloat16* phdst;
        if (row0 < N) {
            hsrc = h1 + (size_t)row0 * HID;
            pdst = g_p1 + (size_t)row0 * MI;
            phdst = g_p1h + (size_t)row0 * MI;
        } else {
            int r0 = row0 - N;
            hsrc = h2 + (size_t)r0 * HID;
            pdst = g_p2 + (size_t)r0 * MI;
            phdst = g_p2h + (size_t)r0 * MI;
        }

        if (tid < 16) rowsq[tid] = 0.0f;
        __syncthreads();   // also protects cs reuse from previous iteration

        wmma::fragment<wmma::accumulator, 16, 16, 8, float> acc0;
        wmma::fragment<wmma::accumulator, 16, 16, 8, float> acc1;
        wmma::fill_fragment(acc0, 0.0f);
        wmma::fill_fragment(acc1, 0.0f);

        for (int k = 0; k < HID; k += 8) {
            wmma::fragment<wmma::matrix_a, 16, 16, 8, wmma::precision::tf32,
                           wmma::row_major> af;
            wmma::load_matrix_sync(af, hsrc + k, HID);
            for (int i = 0; i < af.num_elements; i++)
                af.x[i] = wmma::__float_to_tf32(af.x[i]);

            wmma::fragment<wmma::matrix_b, 16, 16, 8, wmma::precision::tf32,
                           wmma::row_major> bf0;
            wmma::fragment<wmma::matrix_b, 16, 16, 8, wmma::precision::tf32,
                           wmma::row_major> bf1;
            wmma::load_matrix_sync(bf0, W + (size_t)k * MI + n0, MI);
            wmma::load_matrix_sync(bf1, W + (size_t)k * MI + n0 + 16, MI);
            for (int i = 0; i < bf0.num_elements; i++)
                bf0.x[i] = wmma::__float_to_tf32(bf0.x[i]);
            for (int i = 0; i < bf1.num_elements; i++)
                bf1.x[i] = wmma::__float_to_tf32(bf1.x[i]);

            wmma::mma_sync(acc0, af, bf0, acc0);
            wmma::mma_sync(acc1, af, bf1, acc1);
        }

        wmma::store_matrix_sync(cs + n0, acc0, PJ_LD, wmma::mem_row_major);
        wmma::store_matrix_sync(cs + n0 + 16, acc1, PJ_LD, wmma::mem_row_major);
        __syncthreads();

        int r = tid >> 3;
        int c0 = (tid & 7) * 16;
        float vals[16];
        float sq = 0.0f;
        for (int c = 0; c < 16; c++) {
            float v = cs[r * PJ_LD + c0 + c] + bias[c0 + c];
            v = fmaxf(v, 0.0f);
            vals[c] = v;
            sq += v * v;
        }
        atomicAdd(&rowsq[r], sq);
        __syncthreads();

        float s = rsqrtf(rowsq[r]);
        for (int c = 0; c < 16; c++) {
            float o = vals[c] * s;
            pdst[(size_t)r * MI + c0 + c] = o;
            phdst[(size_t)r * MI + c0 + c] = __float2bfloat16_rn(o);
        }
    }
}

// ============ sim kernel (bf16 wmma): exp(dot/T) row + col sums =============
// CTA: 256 threads = 8 warps (4M x 2N); warp tile 32x64; 128x128 CTA tile,
// K=128 resident. Pure register epilogue (accumulator lane mapping verified
// by the Round-7 runtime probe on this chip/compiler):
//   x[e] -> row = (lane>>2) + ((e>>1)&1)*8
//           col = (lane&3)*2 + (e&1) + ((e>>2)&1)*8
#define SLD 136            // A/B smem row stride in bf16 elements
#define SIM_SMEM (2*128*SLD*2)   // 69632 bytes

__global__ void __launch_bounds__(256, 2) sim_kernel() {
    extern __shared__ unsigned char dynsm[];
    __nv_bfloat16* As = (__nv_bfloat16*)dynsm;
    __nv_bfloat16* Bs = As + 128 * SLD;
    __shared__ float rowred[128];
    __shared__ float colred[128];

    int tid = threadIdx.x;
    int warp = tid >> 5;
    int lane = tid & 31;
    int wm = warp >> 1;          // 0..3  (rows wm*32)
    int wn = warp & 1;           // 0..1  (cols wn*64)
    int i0 = blockIdx.y * 128;
    int j0 = blockIdx.x * 128;

    const uint4* srcA = (const uint4*)(g_p1h + (size_t)i0 * MI);
    const uint4* srcB = (const uint4*)(g_p2h + (size_t)j0 * MI);
    for (int idx = tid; idx < 2048; idx += 256) {
        int r = idx >> 4;
        int ch = idx & 15;
        *(uint4*)(As + r * SLD + ch * 8) = srcA[idx];
        *(uint4*)(Bs + r * SLD + ch * 8) = srcB[idx];
    }
    if (tid < 128) {
        rowred[tid] = 0.0f;
        colred[tid] = 0.0f;
    }
    __syncthreads();

    wmma::fragment<wmma::accumulator, 16, 16, 16, float> acc[2][4];
    #pragma unroll
    for (int mt = 0; mt < 2; mt++) {
        #pragma unroll
        for (int nt = 0; nt < 4; nt++)
            wmma::fill_fragment(acc[mt][nt], 0.0f);
    }

    const __nv_bfloat16* abase = As + (wm * 32) * SLD;
    const __nv_bfloat16* bbase = Bs + (wn * 64) * SLD;

    #pragma unroll
    for (int k = 0; k < 8; k++) {
        wmma::fragment<wmma::matrix_a, 16, 16, 16, __nv_bfloat16,
                       wmma::row_major> af0;
        wmma::fragment<wmma::matrix_a, 16, 16, 16, __nv_bfloat16,
                       wmma::row_major> af1;
        wmma::load_matrix_sync(af0, abase + k * 16, SLD);
        wmma::load_matrix_sync(af1, abase + 16 * SLD + k * 16, SLD);
        #pragma unroll
        for (int nt = 0; nt < 4; nt++) {
            wmma::fragment<wmma::matrix_b, 16, 16, 16, __nv_bfloat16,
                           wmma::col_major> bf;
            wmma::load_matrix_sync(bf, bbase + nt * 16 * SLD + k * 16, SLD);
            wmma::mma_sync(acc[0][nt], af0, bf, acc[0][nt]);
            wmma::mma_sync(acc[1][nt], af1, bf, acc[1][nt]);
        }
    }

    // ---- register epilogue: exp + row/col sums via shuffles ----
    float cs0[4];
    float cs1[4];
    float cs2[4];
    float cs3[4];
    #pragma unroll
    for (int nt = 0; nt < 4; nt++) {
        cs0[nt] = 0.0f;
        cs1[nt] = 0.0f;
        cs2[nt] = 0.0f;
        cs3[nt] = 0.0f;
    }
    #pragma unroll
    for (int mt = 0; mt < 2; mt++) {
        float rlo = 0.0f;
        float rhi = 0.0f;
        #pragma unroll
        for (int nt = 0; nt < 4; nt++) {
            float e0 = __expf(2.0f * acc[mt][nt].x[0]);
            float e1 = __expf(2.0f * acc[mt][nt].x[1]);
            float e2 = __expf(2.0f * acc[mt][nt].x[2]);
            float e3 = __expf(2.0f * acc[mt][nt].x[3]);
            float e4 = __expf(2.0f * acc[mt][nt].x[4]);
            float e5 = __expf(2.0f * acc[mt][nt].x[5]);
            float e6 = __expf(2.0f * acc[mt][nt].x[6]);
            float e7 = __expf(2.0f * acc[mt][nt].x[7]);
            rlo += e0 + e1 + e4 + e5;     // row (lane>>2)
            rhi += e2 + e3 + e6 + e7;     // row (lane>>2)+8
            cs0[nt] += e0 + e2;           // col base
            cs1[nt] += e1 + e3;           // col base+1
            cs2[nt] += e4 + e6;           // col base+8
            cs3[nt] += e5 + e7;           // col base+9
        }
        rlo += __shfl_xor_sync(0xffffffffu, rlo, 1);
        rlo += __shfl_xor_sync(0xffffffffu, rlo, 2);
        rhi += __shfl_xor_sync(0xffffffffu, rhi, 1);
        rhi += __shfl_xor_sync(0xffffffffu, rhi, 2);
        if ((lane & 3) == 0) {
            int r = wm * 32 + mt * 16 + (lane >> 2);
            atomicAdd(&rowred[r], rlo);
            atomicAdd(&rowred[r + 8], rhi);
        }
    }
    #pragma unroll
    for (int nt = 0; nt < 4; nt++) {
        float v0 = cs0[nt];
        float v1 = cs1[nt];
        float v2 = cs2[nt];
        float v3 = cs3[nt];
        v0 += __shfl_xor_sync(0xffffffffu, v0, 4);
        v0 += __shfl_xor_sync(0xffffffffu, v0, 8);
        v0 += __shfl_xor_sync(0xffffffffu, v0, 16);
        v1 += __shfl_xor_sync(0xffffffffu, v1, 4);
        v1 += __shfl_xor_sync(0xffffffffu, v1, 8);
        v1 += __shfl_xor_sync(0xffffffffu, v1, 16);
        v2 += __shfl_xor_sync(0xffffffffu, v2, 4);
        v2 += __shfl_xor_sync(0xffffffffu, v2, 8);
        v2 += __shfl_xor_sync(0xffffffffu, v2, 16);
        v3 += __shfl_xor_sync(0xffffffffu, v3, 4);
        v3 += __shfl_xor_sync(0xffffffffu, v3, 8);
        v3 += __shfl_xor_sync(0xffffffffu, v3, 16);
        if (lane < 4) {
            int cb = wn * 64 + nt * 16 + lane * 2;
            atomicAdd(&colred[cb], v0);
            atomicAdd(&colred[cb + 1], v1);
            atomicAdd(&colred[cb + 8], v2);
            atomicAdd(&colred[cb + 9], v3);
        }
    }
    __syncthreads();

    if (tid < 128) {
        atomicAdd(&g_stats[RS1 + i0 + tid], rowred[tid]);
        atomicAdd(&g_stats[RS2 + j0 + tid], colred[tid]);
    }
}

// ---------------- positives: warp per edge, both directions (fp32) ---------
__global__ void pos_kernel(const int* __restrict__ pr, const int* __restrict__ pc) {
    int e = (blockIdx.x * blockDim.x + threadIdx.x) >> 5;
    int lane = threadIdx.x & 31;
    if (e >= NEDGE) return;
    int r = pr[e];
    int c = pc[e];
    const float4* p1r = (const float4*)(g_p1 + (size_t)r * MI);
    const float4* p2r = (const float4*)(g_p2 + (size_t)r * MI);
    const float4* p1c = (const float4*)(g_p1 + (size_t)c * MI);
    const float4* p2c = (const float4*)(g_p2 + (size_t)c * MI);
    float4 a1 = p1r[lane];
    float4 b2 = p2c[lane];
    float4 a2 = p2r[lane];
    float4 b1 = p1c[lane];
    float d1 = a1.x * b2.x + a1.y * b2.y + a1.z * b2.z + a1.w * b2.w;
    float d2 = a2.x * b1.x + a2.y * b1.y + a2.z * b1.z + a2.w * b1.w;
    for (int o = 16; o > 0; o >>= 1) {
        d1 += __shfl_down_sync(0xffffffffu, d1, o);
        d2 += __shfl_down_sync(0xffffffffu, d2, o);
    }
    if (lane == 0) {
        float s1 = 2.0f * d1;
        float s2 = 2.0f * d2;
        atomicAdd(&g_stats[SP1 + r], s1);
        atomicAdd(&g_stats[PS1 + r], __expf(s1));
        atomicAdd(&g_stats[SP2 + r], s2);
        atomicAdd(&g_stats[PS2 + r], __expf(s2));
    }
}

// ---------------- final loss reduction ----------------
__global__ void loss_kernel(float* out) {
    float acc = 0.f;
    const float invcnt = 0.25f;   // exactly 4 positives per row by construction
    for (int i = threadIdx.x; i < N; i += blockDim.x) {
        float per1 = g_stats[SP1 + i] * invcnt
                   - __logf(g_stats[RS1 + i] - g_stats[PS1 + i]);
        float per2 = g_stats[SP2 + i] * invcnt
                   - __logf(g_stats[RS2 + i] - g_stats[PS2 + i]);
        acc += per1 + per2;
    }
    __shared__ float red[32];
    for (int o = 16; o > 0; o >>= 1)
        acc += __shfl_down_sync(0xffffffffu, acc, o);
    if ((threadIdx.x & 31) == 0) red[threadIdx.x >> 5] = acc;
    __syncthreads();
    if (threadIdx.x == 0) {
        float t = 0.f;
        int nw = blockDim.x >> 5;
        for (int w = 0; w < nw; w++) t += red[w];
        out[0] = -0.5f * t / (float)N;
    }
}

// ---------------- launch ----------------
extern "C" void kernel_launch(void* const* d_in, const int* in_sizes, int n_in,
                              void* d_out, int out_size) {
    const float* h1 = (const float*)d_in[0];
    const float* h2 = (const float*)d_in[1];
    const float* W  = (const float*)d_in[2];
    const float* b  = (const float*)d_in[3];
    const int*   pr = (const int*)d_in[4];
    const int*   pc = (const int*)d_in[5];
    float* out = (float*)d_out;

    proj_kernel<<<(2 * N) / 64, 128>>>(h1, h2, W, b);
    pos_kernel<<<(NEDGE * 32) / 256, 256>>>(pr, pc);
    nop_kernel<<<1, 32>>>();

    cudaFuncSetAttribute(sim_kernel,
                         cudaFuncAttributeMaxDynamicSharedMemorySize, SIM_SMEM);
    dim3 simgrid(N / 128, N / 128);
    sim_kernel<<<simgrid, 256, SIM_SMEM>>>();

    loss_kernel<<<1, 1024>>>(out);
}

// round 14
// speedup vs baseline: 1.9955x; 1.0172x over previous
#include <cuda_runtime.h>
#include <cuda_bf16.h>
#include <mma.h>
#include <math.h>

using namespace nvcuda;

#define N 16384
#define HID 256
#define MI 128
#define NEDGE (N*4)

// stats layout inside g_stats
#define RS1 0
#define RS2 (N)
#define PS1 (2*N)
#define PS2 (3*N)
#define SP1 (4*N)
#define SP2 (5*N)

// ---------------- scratch (device globals; no allocation allowed) ----------
__device__ float g_p1[(size_t)N*MI];
__device__ float g_p2[(size_t)N*MI];
__device__ __nv_bfloat16 g_p1h[(size_t)N*MI];
__device__ __nv_bfloat16 g_p2h[(size_t)N*MI];
__device__ float g_stats[6*N];

// ---------------- nop spacer (positions sim as the 4th launch for ncu) -----
__global__ void nop_kernel() {}

// ============ projection (tf32 wmma): p = l2norm(relu(h@W + b)) =============
// CTA: 32 rows x 128 cols, 256 threads = 8 warps in TWO PARALLEL groups:
// warps 0-3 -> rows 0-15, warps 4-7 -> rows 16-31 (each group spans all 128
// cols). Halves W L2 traffic vs 16-row CTAs without serializing row tiles.
// Grid 1024; each block zeroes 96 floats of g_stats (1024*96 = 6*N).
#define PJ_LD 132

__global__ void __launch_bounds__(256, 1) proj_kernel(
        const float* __restrict__ h1, const float* __restrict__ h2,
        const float* __restrict__ W, const float* __restrict__ bias) {
    __shared__ float cs[32 * PJ_LD];
    __shared__ float rowsq[32];

    int tid = threadIdx.x;
    int warp = tid >> 5;
    int wg = warp >> 2;          // 0..1 row group
    int wi = warp & 3;           // 0..3 col range wi*32
    int row0 = blockIdx.x * 32 + wg * 16;

    if (tid < 96) g_stats[blockIdx.x * 96 + tid] = 0.0f;

    const float* hsrc;
    float* pdst;
    __nv_bfloat16* phdst;
    if (row0 < N) {
        hsrc = h1 + (size_t)row0 * HID;
        pdst = g_p1 + (size_t)row0 * MI;
        phdst = g_p1h + (size_t)row0 * MI;
    } else {
        int r0 = row0 - N;
        hsrc = h2 + (size_t)r0 * HID;
        pdst = g_p2 + (size_t)r0 * MI;
        phdst = g_p2h + (size_t)r0 * MI;
    }

    wmma::fragment<wmma::accumulator, 16, 16, 8, float> acc0;
    wmma::fragment<wmma::accumulator, 16, 16, 8, float> acc1;
    wmma::fill_fragment(acc0, 0.0f);
    wmma::fill_fragment(acc1, 0.0f);

    int n0 = wi * 32;
    for (int k = 0; k < HID; k += 8) {
        wmma::fragment<wmma::matrix_a, 16, 16, 8, wmma::precision::tf32,
                       wmma::row_major> af;
        wmma::load_matrix_sync(af, hsrc + k, HID);
        for (int i = 0; i < af.num_elements; i++)
            af.x[i] = wmma::__float_to_tf32(af.x[i]);

        wmma::fragment<wmma::matrix_b, 16, 16, 8, wmma::precision::tf32,
                       wmma::row_major> bf0;
        wmma::fragment<wmma::matrix_b, 16, 16, 8, wmma::precision::tf32,
                       wmma::row_major> bf1;
        wmma::load_matrix_sync(bf0, W + (size_t)k * MI + n0, MI);
        wmma::load_matrix_sync(bf1, W + (size_t)k * MI + n0 + 16, MI);
        for (int i = 0; i < bf0.num_elements; i++)
            bf0.x[i] = wmma::__float_to_tf32(bf0.x[i]);
        for (int i = 0; i < bf1.num_elements; i++)
            bf1.x[i] = wmma::__float_to_tf32(bf1.x[i]);

        wmma::mma_sync(acc0, af, bf0, acc0);
        wmma::mma_sync(acc1, af, bf1, acc1);
    }

    float* csg = cs + wg * 16 * PJ_LD;
    wmma::store_matrix_sync(csg + n0, acc0, PJ_LD, wmma::mem_row_major);
    wmma::store_matrix_sync(csg + n0 + 16, acc1, PJ_LD, wmma::mem_row_major);
    if (tid < 32) rowsq[tid] = 0.0f;
    __syncthreads();

    // 256 threads cover 32 rows x 128 cols: row = tid>>3, 16 cols each
    int r = tid >> 3;
    int c0 = (tid & 7) * 16;
    float vals[16];
    float sq = 0.0f;
    for (int c = 0; c < 16; c++) {
        float v = cs[r * PJ_LD + c0 + c] + bias[c0 + c];
        v = fmaxf(v, 0.0f);
        vals[c] = v;
        sq += v * v;
    }
    atomicAdd(&rowsq[r], sq);
    __syncthreads();

    // output pointers per half (r 0..31 spans both groups; recompute base)
    int rowg = blockIdx.x * 32 + r;
    float* pout;
    __nv_bfloat16* phout;
    if (rowg < N) {
        pout = g_p1 + (size_t)rowg * MI;
        phout = g_p1h + (size_t)rowg * MI;
    } else {
        pout = g_p2 + (size_t)(rowg - N) * MI;
        phout = g_p2h + (size_t)(rowg - N) * MI;
    }
    float s = rsqrtf(rowsq[r]);
    for (int c = 0; c < 16; c++) {
        float o = vals[c] * s;
        pout[c0 + c] = o;
        phout[c0 + c] = __float2bfloat16_rn(o);
    }
}

// ============ sim kernel (bf16 wmma): exp(dot/T) row + col sums =============
// CTA: 256 threads = 8 warps (4M x 2N); warp tile 32x64; 128x128 CTA tile,
// K=128 resident. Pure register epilogue (accumulator lane mapping verified
// by the Round-7 runtime probe on this chip/compiler):
//   x[e] -> row = (lane>>2) + ((e>>1)&1)*8
//           col = (lane&3)*2 + (e&1) + ((e>>2)&1)*8
#define SLD 136            // A/B smem row stride in bf16 elements
#define SIM_SMEM (2*128*SLD*2)   // 69632 bytes

__global__ void __launch_bounds__(256, 2) sim_kernel() {
    extern __shared__ unsigned char dynsm[];
    __nv_bfloat16* As = (__nv_bfloat16*)dynsm;
    __nv_bfloat16* Bs = As + 128 * SLD;
    __shared__ float rowred[128];
    __shared__ float colred[128];

    int tid = threadIdx.x;
    int warp = tid >> 5;
    int lane = tid & 31;
    int wm = warp >> 1;          // 0..3  (rows wm*32)
    int wn = warp & 1;           // 0..1  (cols wn*64)
    int i0 = blockIdx.y * 128;
    int j0 = blockIdx.x * 128;

    const uint4* srcA = (const uint4*)(g_p1h + (size_t)i0 * MI);
    const uint4* srcB = (const uint4*)(g_p2h + (size_t)j0 * MI);
    for (int idx = tid; idx < 2048; idx += 256) {
        int r = idx >> 4;
        int ch = idx & 15;
        *(uint4*)(As + r * SLD + ch * 8) = srcA[idx];
        *(uint4*)(Bs + r * SLD + ch * 8) = srcB[idx];
    }
    if (tid < 128) {
        rowred[tid] = 0.0f;
        colred[tid] = 0.0f;
    }
    __syncthreads();

    wmma::fragment<wmma::accumulator, 16, 16, 16, float> acc[2][4];
    #pragma unroll
    for (int mt = 0; mt < 2; mt++) {
        #pragma unroll
        for (int nt = 0; nt < 4; nt++)
            wmma::fill_fragment(acc[mt][nt], 0.0f);
    }

    const __nv_bfloat16* abase = As + (wm * 32) * SLD;
    const __nv_bfloat16* bbase = Bs + (wn * 64) * SLD;

    #pragma unroll
    for (int k = 0; k < 8; k++) {
        wmma::fragment<wmma::matrix_a, 16, 16, 16, __nv_bfloat16,
                       wmma::row_major> af0;
        wmma::fragment<wmma::matrix_a, 16, 16, 16, __nv_bfloat16,
                       wmma::row_major> af1;
        wmma::load_matrix_sync(af0, abase + k * 16, SLD);
        wmma::load_matrix_sync(af1, abase + 16 * SLD + k * 16, SLD);
        #pragma unroll
        for (int nt = 0; nt < 4; nt++) {
            wmma::fragment<wmma::matrix_b, 16, 16, 16, __nv_bfloat16,
                           wmma::col_major> bf;
            wmma::load_matrix_sync(bf, bbase + nt * 16 * SLD + k * 16, SLD);
            wmma::mma_sync(acc[0][nt], af0, bf, acc[0][nt]);
            wmma::mma_sync(acc[1][nt], af1, bf, acc[1][nt]);
        }
    }

    // ---- register epilogue: exp + row/col sums via shuffles ----
    float cs0[4];
    float cs1[4];
    float cs2[4];
    float cs3[4];
    #pragma unroll
    for (int nt = 0; nt < 4; nt++) {
        cs0[nt] = 0.0f;
        cs1[nt] = 0.0f;
        cs2[nt] = 0.0f;
        cs3[nt] = 0.0f;
    }
    #pragma unroll
    for (int mt = 0; mt < 2; mt++) {
        float rlo = 0.0f;
        float rhi = 0.0f;
        #pragma unroll
        for (int nt = 0; nt < 4; nt++) {
            float e0 = __expf(2.0f * acc[mt][nt].x[0]);
            float e1 = __expf(2.0f * acc[mt][nt].x[1]);
            float e2 = __expf(2.0f * acc[mt][nt].x[2]);
            float e3 = __expf(2.0f * acc[mt][nt].x[3]);
            float e4 = __expf(2.0f * acc[mt][nt].x[4]);
            float e5 = __expf(2.0f * acc[mt][nt].x[5]);
            float e6 = __expf(2.0f * acc[mt][nt].x[6]);
            float e7 = __expf(2.0f * acc[mt][nt].x[7]);
            rlo += e0 + e1 + e4 + e5;     // row (lane>>2)
            rhi += e2 + e3 + e6 + e7;     // row (lane>>2)+8
            cs0[nt] += e0 + e2;           // col base
            cs1[nt] += e1 + e3;           // col base+1
            cs2[nt] += e4 + e6;           // col base+8
            cs3[nt] += e5 + e7;           // col base+9
        }
        rlo += __shfl_xor_sync(0xffffffffu, rlo, 1);
        rlo += __shfl_xor_sync(0xffffffffu, rlo, 2);
        rhi += __shfl_xor_sync(0xffffffffu, rhi, 1);
        rhi += __shfl_xor_sync(0xffffffffu, rhi, 2);
        if ((lane & 3) == 0) {
            int r = wm * 32 + mt * 16 + (lane >> 2);
            atomicAdd(&rowred[r], rlo);
            atomicAdd(&rowred[r + 8], rhi);
        }
    }
    #pragma unroll
    for (int nt = 0; nt < 4; nt++) {
        float v0 = cs0[nt];
        float v1 = cs1[nt];
        float v2 = cs2[nt];
        float v3 = cs3[nt];
        v0 += __shfl_xor_sync(0xffffffffu, v0, 4);
        v0 += __shfl_xor_sync(0xffffffffu, v0, 8);
        v0 += __shfl_xor_sync(0xffffffffu, v0, 16);
        v1 += __shfl_xor_sync(0xffffffffu, v1, 4);
        v1 += __shfl_xor_sync(0xffffffffu, v1, 8);
        v1 += __shfl_xor_sync(0xffffffffu, v1, 16);
        v2 += __shfl_xor_sync(0xffffffffu, v2, 4);
        v2 += __shfl_xor_sync(0xffffffffu, v2, 8);
        v2 += __shfl_xor_sync(0xffffffffu, v2, 16);
        v3 += __shfl_xor_sync(0xffffffffu, v3, 4);
        v3 += __shfl_xor_sync(0xffffffffu, v3, 8);
        v3 += __shfl_xor_sync(0xffffffffu, v3, 16);
        if (lane < 4) {
            int cb = wn * 64 + nt * 16 + lane * 2;
            atomicAdd(&colred[cb], v0);
            atomicAdd(&colred[cb + 1], v1);
            atomicAdd(&colred[cb + 8], v2);
            atomicAdd(&colred[cb + 9], v3);
        }
    }
    __syncthreads();

    if (tid < 128) {
        atomicAdd(&g_stats[RS1 + i0 + tid], rowred[tid]);
        atomicAdd(&g_stats[RS2 + j0 + tid], colred[tid]);
    }
}

// ---------------- positives: warp per edge, both directions (fp32) ---------
__global__ void pos_kernel(const int* __restrict__ pr, const int* __restrict__ pc) {
    int e = (blockIdx.x * blockDim.x + threadIdx.x) >> 5;
    int lane = threadIdx.x & 31;
    if (e >= NEDGE) return;
    int r = pr[e];
    int c = pc[e];
    const float4* p1r = (const float4*)(g_p1 + (size_t)r * MI);
    const float4* p2r = (const float4*)(g_p2 + (size_t)r * MI);
    const float4* p1c = (const float4*)(g_p1 + (size_t)c * MI);
    const float4* p2c = (const float4*)(g_p2 + (size_t)c * MI);
    float4 a1 = p1r[lane];
    float4 b2 = p2c[lane];
    float4 a2 = p2r[lane];
    float4 b1 = p1c[lane];
    float d1 = a1.x * b2.x + a1.y * b2.y + a1.z * b2.z + a1.w * b2.w;
    float d2 = a2.x * b1.x + a2.y * b1.y + a2.z * b1.z + a2.w * b1.w;
    for (int o = 16; o > 0; o >>= 1) {
        d1 += __shfl_down_sync(0xffffffffu, d1, o);
        d2 += __shfl_down_sync(0xffffffffu, d2, o);
    }
    if (lane == 0) {
        float s1 = 2.0f * d1;
        float s2 = 2.0f * d2;
        atomicAdd(&g_stats[SP1 + r], s1);
        atomicAdd(&g_stats[PS1 + r], __expf(s1));
        atomicAdd(&g_stats[SP2 + r], s2);
        atomicAdd(&g_stats[PS2 + r], __expf(s2));
    }
}

// ---------------- final loss reduction ----------------
__global__ void loss_kernel(float* out) {
    float acc = 0.f;
    const float invcnt = 0.25f;   // exactly 4 positives per row by construction
    for (int i = threadIdx.x; i < N; i += blockDim.x) {
        float per1 = g_stats[SP1 + i] * invcnt
                   - __logf(g_stats[RS1 + i] - g_stats[PS1 + i]);
        float per2 = g_stats[SP2 + i] * invcnt
                   - __logf(g_stats[RS2 + i] - g_stats[PS2 + i]);
        acc += per1 + per2;
    }
    __shared__ float red[32];
    for (int o = 16; o > 0; o >>= 1)
        acc += __shfl_down_sync(0xffffffffu, acc, o);
    if ((threadIdx.x & 31) == 0) red[threadIdx.x >> 5] = acc;
    __syncthreads();
    if (threadIdx.x == 0) {
        float t = 0.f;
        int nw = blockDim.x >> 5;
        for (int w = 0; w < nw; w++) t += red[w];
        out[0] = -0.5f * t / (float)N;
    }
}

// ---------------- launch ----------------
extern "C" void kernel_launch(void* const* d_in, const int* in_sizes, int n_in,
                              void* d_out, int out_size) {
    const float* h1 = (const float*)d_in[0];
    const float* h2 = (const float*)d_in[1];
    const float* W  = (const float*)d_in[2];
    const float* b  = (const float*)d_in[3];
    const int*   pr = (const int*)d_in[4];
    const int*   pc = (const int*)d_in[5];
    float* out = (float*)d_out;

    proj_kernel<<<(2 * N) / 32, 256>>>(h1, h2, W, b);
    pos_kernel<<<(NEDGE * 32) / 256, 256>>>(pr, pc);
    nop_kernel<<<1, 32>>>();

    cudaFuncSetAttribute(sim_kernel,
                         cudaFuncAttributeMaxDynamicSharedMemorySize, SIM_SMEM);
    dim3 simgrid(N / 128, N / 128);
    sim_kernel<<<simgrid, 256, SIM_SMEM>>>();

    loss_kernel<<<1, 1024>>>(out);
}

// round 15
// speedup vs baseline: 2.1154x; 1.0601x over previous
#include <cuda_runtime.h>
#include <cuda_bf16.h>
#include <mma.h>
#include <math.h>

using namespace nvcuda;

#define N 16384
#define HID 256
#define MI 128
#define NEDGE (N*4)

// stats layout inside g_stats
#define RS1 0
#define RS2 (N)
#define PS1 (2*N)
#define PS2 (3*N)
#define SP1 (4*N)
#define SP2 (5*N)

// ---------------- scratch (device globals; no allocation allowed) ----------
__device__ float g_p1[(size_t)N*MI];
__device__ float g_p2[(size_t)N*MI];
__device__ __nv_bfloat16 g_p1h[(size_t)N*MI];
__device__ __nv_bfloat16 g_p2h[(size_t)N*MI];
__device__ float g_stats[6*N];
__device__ float g_part[16];

// ============ projection (bf16 wmma, smem-staged): p = l2norm(relu(hW+b)) ===
// CTA: 64 rows x 128 cols, 256 threads = 8 warps (2 row groups x 4 col quads).
// Full W (256x128) converted to bf16 and staged in smem ONCE per CTA; A tile
// 64x256 staged bf16. Mainloop is LDSM+HMMA (k16 x 16 iters). This removes
// the per-fragment global LDG + tf32-convert storm of the old proj.
// Grid 512; each block zeroes 192 floats of g_stats (512*192 = 6*N).
#define WLD 136   // Ws row stride (bf16)
#define ALD 264   // As row stride (bf16)
#define CLD 132   // epilogue staging stride (float)
#define PJ_SMEM (256*WLD*2 + 64*ALD*2)   // 69632 + 33792 = 103424 bytes

__global__ void __launch_bounds__(256, 1) proj_kernel(
        const float* __restrict__ h1, const float* __restrict__ h2,
        const float* __restrict__ W, const float* __restrict__ bias) {
    extern __shared__ unsigned char pj_sm[];
    __nv_bfloat16* Ws = (__nv_bfloat16*)pj_sm;
    __nv_bfloat16* As = Ws + 256 * WLD;
    float* cs = (float*)pj_sm;          // aliases Ws/As after mainloop
    __shared__ float rowsq[64];

    int tid = threadIdx.x;
    int warp = tid >> 5;
    int wg = warp >> 2;          // 0..1 -> rows wg*32
    int wi = warp & 3;           // 0..3 -> cols wi*32
    int blk0 = blockIdx.x * 64;

    if (tid < 192) g_stats[blockIdx.x * 192 + tid] = 0.0f;

    const float* hsrc;
    if (blk0 < N) hsrc = h1 + (size_t)blk0 * HID;
    else          hsrc = h2 + (size_t)(blk0 - N) * HID;

    // stage W (256x128 fp32 -> bf16), 8192 float4 reads
    for (int idx = tid; idx < 8192; idx += 256) {
        int k = idx >> 5;
        int n4 = (idx & 31) * 4;
        float4 v = *(const float4*)(W + (size_t)k * MI + n4);
        __nv_bfloat162 lo;
        lo.x = __float2bfloat16_rn(v.x);
        lo.y = __float2bfloat16_rn(v.y);
        __nv_bfloat162 hi;
        hi.x = __float2bfloat16_rn(v.z);
        hi.y = __float2bfloat16_rn(v.w);
        *(__nv_bfloat162*)(Ws + k * WLD + n4) = lo;
        *(__nv_bfloat162*)(Ws + k * WLD + n4 + 2) = hi;
    }
    // stage A (64x256 fp32 -> bf16), 4096 float4 reads
    for (int idx = tid; idx < 4096; idx += 256) {
        int r = idx >> 6;
        int c4 = (idx & 63) * 4;
        float4 v = *(const float4*)(hsrc + (size_t)r * HID + c4);
        __nv_bfloat162 lo;
        lo.x = __float2bfloat16_rn(v.x);
        lo.y = __float2bfloat16_rn(v.y);
        __nv_bfloat162 hi;
        hi.x = __float2bfloat16_rn(v.z);
        hi.y = __float2bfloat16_rn(v.w);
        *(__nv_bfloat162*)(As + r * ALD + c4) = lo;
        *(__nv_bfloat162*)(As + r * ALD + c4 + 2) = hi;
    }
    __syncthreads();

    wmma::fragment<wmma::accumulator, 16, 16, 16, float> acc[2][2];
    #pragma unroll
    for (int mt = 0; mt < 2; mt++) {
        #pragma unroll
        for (int nt = 0; nt < 2; nt++)
            wmma::fill_fragment(acc[mt][nt], 0.0f);
    }

    const __nv_bfloat16* abase = As + (wg * 32) * ALD;
    const __nv_bfloat16* bbase = Ws + wi * 32;

    #pragma unroll
    for (int k = 0; k < 16; k++) {
        wmma::fragment<wmma::matrix_a, 16, 16, 16, __nv_bfloat16,
                       wmma::row_major> af0;
        wmma::fragment<wmma::matrix_a, 16, 16, 16, __nv_bfloat16,
                       wmma::row_major> af1;
        wmma::load_matrix_sync(af0, abase + k * 16, ALD);
        wmma::load_matrix_sync(af1, abase + 16 * ALD + k * 16, ALD);
        wmma::fragment<wmma::matrix_b, 16, 16, 16, __nv_bfloat16,
                       wmma::row_major> bf0;
        wmma::fragment<wmma::matrix_b, 16, 16, 16, __nv_bfloat16,
                       wmma::row_major> bf1;
        wmma::load_matrix_sync(bf0, bbase + (k * 16) * WLD, WLD);
        wmma::load_matrix_sync(bf1, bbase + (k * 16) * WLD + 16, WLD);
        wmma::mma_sync(acc[0][0], af0, bf0, acc[0][0]);
        wmma::mma_sync(acc[0][1], af0, bf1, acc[0][1]);
        wmma::mma_sync(acc[1][0], af1, bf0, acc[1][0]);
        wmma::mma_sync(acc[1][1], af1, bf1, acc[1][1]);
    }

    __syncthreads();   // Ws/As dead; cs aliases them
    #pragma unroll
    for (int mt = 0; mt < 2; mt++) {
        #pragma unroll
        for (int nt = 0; nt < 2; nt++)
            wmma::store_matrix_sync(
                cs + (wg * 32 + mt * 16) * CLD + wi * 32 + nt * 16,
                acc[mt][nt], CLD, wmma::mem_row_major);
    }
    if (tid < 64) rowsq[tid] = 0.0f;
    __syncthreads();

    // 256 threads cover 64 rows x 128 cols: row = tid>>2, 32 cols each
    int r = tid >> 2;
    int c0 = (tid & 3) * 32;
    float vals[32];
    float sq = 0.0f;
    for (int c = 0; c < 32; c++) {
        float v = cs[r * CLD + c0 + c] + bias[c0 + c];
        v = fmaxf(v, 0.0f);
        vals[c] = v;
        sq += v * v;
    }
    atomicAdd(&rowsq[r], sq);
    __syncthreads();

    int rowg = blk0 + r;
    float* pout;
    __nv_bfloat16* phout;
    if (rowg < N) {
        pout = g_p1 + (size_t)rowg * MI;
        phout = g_p1h + (size_t)rowg * MI;
    } else {
        pout = g_p2 + (size_t)(rowg - N) * MI;
        phout = g_p2h + (size_t)(rowg - N) * MI;
    }
    float s = rsqrtf(rowsq[r]);
    for (int c = 0; c < 32; c++) {
        float o = vals[c] * s;
        pout[c0 + c] = o;
        phout[c0 + c] = __float2bfloat16_rn(o);
    }
}

// ============ sim kernel (bf16 wmma): exp(dot/T) row + col sums =============
// CTA: 256 threads = 8 warps (4M x 2N); warp tile 32x64; 128x128 CTA tile,
// K=128 resident. Pure register epilogue (accumulator lane mapping verified
// by the Round-7 runtime probe on this chip/compiler):
//   x[e] -> row = (lane>>2) + ((e>>1)&1)*8
//           col = (lane&3)*2 + (e&1) + ((e>>2)&1)*8
#define SLD 136            // A/B smem row stride in bf16 elements
#define SIM_SMEM (2*128*SLD*2)   // 69632 bytes

__global__ void __launch_bounds__(256, 2) sim_kernel() {
    extern __shared__ unsigned char dynsm[];
    __nv_bfloat16* As = (__nv_bfloat16*)dynsm;
    __nv_bfloat16* Bs = As + 128 * SLD;
    __shared__ float rowred[128];
    __shared__ float colred[128];

    int tid = threadIdx.x;
    int warp = tid >> 5;
    int lane = tid & 31;
    int wm = warp >> 1;          // 0..3  (rows wm*32)
    int wn = warp & 1;           // 0..1  (cols wn*64)
    int i0 = blockIdx.y * 128;
    int j0 = blockIdx.x * 128;

    const uint4* srcA = (const uint4*)(g_p1h + (size_t)i0 * MI);
    const uint4* srcB = (const uint4*)(g_p2h + (size_t)j0 * MI);
    for (int idx = tid; idx < 2048; idx += 256) {
        int r = idx >> 4;
        int ch = idx & 15;
        *(uint4*)(As + r * SLD + ch * 8) = srcA[idx];
        *(uint4*)(Bs + r * SLD + ch * 8) = srcB[idx];
    }
    if (tid < 128) {
        rowred[tid] = 0.0f;
        colred[tid] = 0.0f;
    }
    __syncthreads();

    wmma::fragment<wmma::accumulator, 16, 16, 16, float> acc[2][4];
    #pragma unroll
    for (int mt = 0; mt < 2; mt++) {
        #pragma unroll
        for (int nt = 0; nt < 4; nt++)
            wmma::fill_fragment(acc[mt][nt], 0.0f);
    }

    const __nv_bfloat16* abase = As + (wm * 32) * SLD;
    const __nv_bfloat16* bbase = Bs + (wn * 64) * SLD;

    #pragma unroll
    for (int k = 0; k < 8; k++) {
        wmma::fragment<wmma::matrix_a, 16, 16, 16, __nv_bfloat16,
                       wmma::row_major> af0;
        wmma::fragment<wmma::matrix_a, 16, 16, 16, __nv_bfloat16,
                       wmma::row_major> af1;
        wmma::load_matrix_sync(af0, abase + k * 16, SLD);
        wmma::load_matrix_sync(af1, abase + 16 * SLD + k * 16, SLD);
        #pragma unroll
        for (int nt = 0; nt < 4; nt++) {
            wmma::fragment<wmma::matrix_b, 16, 16, 16, __nv_bfloat16,
                           wmma::col_major> bf;
            wmma::load_matrix_sync(bf, bbase + nt * 16 * SLD + k * 16, SLD);
            wmma::mma_sync(acc[0][nt], af0, bf, acc[0][nt]);
            wmma::mma_sync(acc[1][nt], af1, bf, acc[1][nt]);
        }
    }

    // ---- register epilogue: exp + row/col sums via shuffles ----
    float cs0[4];
    float cs1[4];
    float cs2[4];
    float cs3[4];
    #pragma unroll
    for (int nt = 0; nt < 4; nt++) {
        cs0[nt] = 0.0f;
        cs1[nt] = 0.0f;
        cs2[nt] = 0.0f;
        cs3[nt] = 0.0f;
    }
    #pragma unroll
    for (int mt = 0; mt < 2; mt++) {
        float rlo = 0.0f;
        float rhi = 0.0f;
        #pragma unroll
        for (int nt = 0; nt < 4; nt++) {
            float e0 = __expf(2.0f * acc[mt][nt].x[0]);
            float e1 = __expf(2.0f * acc[mt][nt].x[1]);
            float e2 = __expf(2.0f * acc[mt][nt].x[2]);
            float e3 = __expf(2.0f * acc[mt][nt].x[3]);
            float e4 = __expf(2.0f * acc[mt][nt].x[4]);
            float e5 = __expf(2.0f * acc[mt][nt].x[5]);
            float e6 = __expf(2.0f * acc[mt][nt].x[6]);
            float e7 = __expf(2.0f * acc[mt][nt].x[7]);
            rlo += e0 + e1 + e4 + e5;     // row (lane>>2)
            rhi += e2 + e3 + e6 + e7;     // row (lane>>2)+8
            cs0[nt] += e0 + e2;           // col base
            cs1[nt] += e1 + e3;           // col base+1
            cs2[nt] += e4 + e6;           // col base+8
            cs3[nt] += e5 + e7;           // col base+9
        }
        rlo += __shfl_xor_sync(0xffffffffu, rlo, 1);
        rlo += __shfl_xor_sync(0xffffffffu, rlo, 2);
        rhi += __shfl_xor_sync(0xffffffffu, rhi, 1);
        rhi += __shfl_xor_sync(0xffffffffu, rhi, 2);
        if ((lane & 3) == 0) {
            int r = wm * 32 + mt * 16 + (lane >> 2);
            atomicAdd(&rowred[r], rlo);
            atomicAdd(&rowred[r + 8], rhi);
        }
    }
    #pragma unroll
    for (int nt = 0; nt < 4; nt++) {
        float v0 = cs0[nt];
        float v1 = cs1[nt];
        float v2 = cs2[nt];
        float v3 = cs3[nt];
        v0 += __shfl_xor_sync(0xffffffffu, v0, 4);
        v0 += __shfl_xor_sync(0xffffffffu, v0, 8);
        v0 += __shfl_xor_sync(0xffffffffu, v0, 16);
        v1 += __shfl_xor_sync(0xffffffffu, v1, 4);
        v1 += __shfl_xor_sync(0xffffffffu, v1, 8);
        v1 += __shfl_xor_sync(0xffffffffu, v1, 16);
        v2 += __shfl_xor_sync(0xffffffffu, v2, 4);
        v2 += __shfl_xor_sync(0xffffffffu, v2, 8);
        v2 += __shfl_xor_sync(0xffffffffu, v2, 16);
        v3 += __shfl_xor_sync(0xffffffffu, v3, 4);
        v3 += __shfl_xor_sync(0xffffffffu, v3, 8);
        v3 += __shfl_xor_sync(0xffffffffu, v3, 16);
        if (lane < 4) {
            int cb = wn * 64 + nt * 16 + lane * 2;
            atomicAdd(&colred[cb], v0);
            atomicAdd(&colred[cb + 1], v1);
            atomicAdd(&colred[cb + 8], v2);
            atomicAdd(&colred[cb + 9], v3);
        }
    }
    __syncthreads();

    if (tid < 128) {
        atomicAdd(&g_stats[RS1 + i0 + tid], rowred[tid]);
        atomicAdd(&g_stats[RS2 + j0 + tid], colred[tid]);
    }
}

// ---------------- positives: warp per edge, both directions (fp32) ---------
__global__ void pos_kernel(const int* __restrict__ pr, const int* __restrict__ pc) {
    int e = (blockIdx.x * blockDim.x + threadIdx.x) >> 5;
    int lane = threadIdx.x & 31;
    if (e >= NEDGE) return;
    int r = pr[e];
    int c = pc[e];
    const float4* p1r = (const float4*)(g_p1 + (size_t)r * MI);
    const float4* p2r = (const float4*)(g_p2 + (size_t)r * MI);
    const float4* p1c = (const float4*)(g_p1 + (size_t)c * MI);
    const float4* p2c = (const float4*)(g_p2 + (size_t)c * MI);
    float4 a1 = p1r[lane];
    float4 b2 = p2c[lane];
    float4 a2 = p2r[lane];
    float4 b1 = p1c[lane];
    float d1 = a1.x * b2.x + a1.y * b2.y + a1.z * b2.z + a1.w * b2.w;
    float d2 = a2.x * b1.x + a2.y * b1.y + a2.z * b1.z + a2.w * b1.w;
    for (int o = 16; o > 0; o >>= 1) {
        d1 += __shfl_down_sync(0xffffffffu, d1, o);
        d2 += __shfl_down_sync(0xffffffffu, d2, o);
    }
    if (lane == 0) {
        float s1 = 2.0f * d1;
        float s2 = 2.0f * d2;
        atomicAdd(&g_stats[SP1 + r], s1);
        atomicAdd(&g_stats[PS1 + r], __expf(s1));
        atomicAdd(&g_stats[SP2 + r], s2);
        atomicAdd(&g_stats[PS2 + r], __expf(s2));
    }
}

// ---------------- loss: stage 1 over 16 blocks, stage 2 tiny ---------------
__global__ void loss_part_kernel() {
    float acc = 0.f;
    const float invcnt = 0.25f;
    int base = blockIdx.x * 1024;
    for (int it = 0; it < 4; it++) {
        int i = base + it * 256 + threadIdx.x;
        float per1 = g_stats[SP1 + i] * invcnt
                   - __logf(g_stats[RS1 + i] - g_stats[PS1 + i]);
        float per2 = g_stats[SP2 + i] * invcnt
                   - __logf(g_stats[RS2 + i] - g_stats[PS2 + i]);
        acc += per1 + per2;
    }
    __shared__ float red[8];
    for (int o = 16; o > 0; o >>= 1)
        acc += __shfl_down_sync(0xffffffffu, acc, o);
    if ((threadIdx.x & 31) == 0) red[threadIdx.x >> 5] = acc;
    __syncthreads();
    if (threadIdx.x == 0) {
        float t = 0.f;
        for (int w = 0; w < 8; w++) t += red[w];
        g_part[blockIdx.x] = t;
    }
}

__global__ void loss_final_kernel(float* out) {
    if (threadIdx.x == 0) {
        float t = 0.f;
        for (int b = 0; b < 16; b++) t += g_part[b];
        out[0] = -0.5f * t / (float)N;
    }
}

// ---------------- launch ----------------
extern "C" void kernel_launch(void* const* d_in, const int* in_sizes, int n_in,
                              void* d_out, int out_size) {
    const float* h1 = (const float*)d_in[0];
    const float* h2 = (const float*)d_in[1];
    const float* W  = (const float*)d_in[2];
    const float* b  = (const float*)d_in[3];
    const int*   pr = (const int*)d_in[4];
    const int*   pc = (const int*)d_in[5];
    float* out = (float*)d_out;

    cudaFuncSetAttribute(proj_kernel,
                         cudaFuncAttributeMaxDynamicSharedMemorySize, PJ_SMEM);
    proj_kernel<<<(2 * N) / 64, 256, PJ_SMEM>>>(h1, h2, W, b);

    pos_kernel<<<(NEDGE * 32) / 256, 256>>>(pr, pc);

    cudaFuncSetAttribute(sim_kernel,
                         cudaFuncAttributeMaxDynamicSharedMemorySize, SIM_SMEM);
    dim3 simgrid(N / 128, N / 128);
    sim_kernel<<<simgrid, 256, SIM_SMEM>>>();

    loss_part_kernel<<<16, 256>>>();
    loss_final_kernel<<<1, 32>>>(out);
}

// round 16
// speedup vs baseline: 2.3845x; 1.1272x over previous
#include <cuda_runtime.h>
#include <cuda_bf16.h>
#include <mma.h>
#include <math.h>

using namespace nvcuda;

#define N 16384
#define HID 256
#define MI 128
#define NEDGE (N*4)

// stats layout inside g_stats
#define RS1 0
#define RS2 (N)
#define PS1 (2*N)
#define PS2 (3*N)
#define SP1 (4*N)
#define SP2 (5*N)

// ---------------- scratch (device globals; no allocation allowed) ----------
__device__ float g_p1[(size_t)N*MI];
__device__ float g_p2[(size_t)N*MI];
__device__ __nv_bfloat16 g_p1h[(size_t)N*MI];
__device__ __nv_bfloat16 g_p2h[(size_t)N*MI];
__device__ float g_stats[6*N];
__device__ float g_part[16];

// ============ projection (bf16 wmma, smem-staged): p = l2norm(relu(hW+b)) ===
// CTA: 64 rows x 128 cols, 256 threads = 8 warps (2 row groups x 4 col quads).
// Full W staged bf16 in smem once per CTA. Grid 512; each block zeroes 192
// floats of g_stats (512*192 = 6*N).
#define WLD 136   // Ws row stride (bf16)
#define ALD 264   // As row stride (bf16)
#define CLD 132   // epilogue staging stride (float)
#define PJ_SMEM (256*WLD*2 + 64*ALD*2)   // 103424 bytes

__global__ void __launch_bounds__(256, 1) proj_kernel(
        const float* __restrict__ h1, const float* __restrict__ h2,
        const float* __restrict__ W, const float* __restrict__ bias) {
    extern __shared__ unsigned char pj_sm[];
    __nv_bfloat16* Ws = (__nv_bfloat16*)pj_sm;
    __nv_bfloat16* As = Ws + 256 * WLD;
    float* cs = (float*)pj_sm;          // aliases Ws/As after mainloop
    __shared__ float rowsq[64];

    int tid = threadIdx.x;
    int warp = tid >> 5;
    int wg = warp >> 2;          // 0..1 -> rows wg*32
    int wi = warp & 3;           // 0..3 -> cols wi*32
    int blk0 = blockIdx.x * 64;

    if (tid < 192) g_stats[blockIdx.x * 192 + tid] = 0.0f;

    const float* hsrc;
    if (blk0 < N) hsrc = h1 + (size_t)blk0 * HID;
    else          hsrc = h2 + (size_t)(blk0 - N) * HID;

    for (int idx = tid; idx < 8192; idx += 256) {
        int k = idx >> 5;
        int n4 = (idx & 31) * 4;
        float4 v = *(const float4*)(W + (size_t)k * MI + n4);
        __nv_bfloat162 lo;
        lo.x = __float2bfloat16_rn(v.x);
        lo.y = __float2bfloat16_rn(v.y);
        __nv_bfloat162 hi;
        hi.x = __float2bfloat16_rn(v.z);
        hi.y = __float2bfloat16_rn(v.w);
        *(__nv_bfloat162*)(Ws + k * WLD + n4) = lo;
        *(__nv_bfloat162*)(Ws + k * WLD + n4 + 2) = hi;
    }
    for (int idx = tid; idx < 4096; idx += 256) {
        int r = idx >> 6;
        int c4 = (idx & 63) * 4;
        float4 v = *(const float4*)(hsrc + (size_t)r * HID + c4);
        __nv_bfloat162 lo;
        lo.x = __float2bfloat16_rn(v.x);
        lo.y = __float2bfloat16_rn(v.y);
        __nv_bfloat162 hi;
        hi.x = __float2bfloat16_rn(v.z);
        hi.y = __float2bfloat16_rn(v.w);
        *(__nv_bfloat162*)(As + r * ALD + c4) = lo;
        *(__nv_bfloat162*)(As + r * ALD + c4 + 2) = hi;
    }
    __syncthreads();

    wmma::fragment<wmma::accumulator, 16, 16, 16, float> acc[2][2];
    #pragma unroll
    for (int mt = 0; mt < 2; mt++) {
        #pragma unroll
        for (int nt = 0; nt < 2; nt++)
            wmma::fill_fragment(acc[mt][nt], 0.0f);
    }

    const __nv_bfloat16* abase = As + (wg * 32) * ALD;
    const __nv_bfloat16* bbase = Ws + wi * 32;

    #pragma unroll
    for (int k = 0; k < 16; k++) {
        wmma::fragment<wmma::matrix_a, 16, 16, 16, __nv_bfloat16,
                       wmma::row_major> af0;
        wmma::fragment<wmma::matrix_a, 16, 16, 16, __nv_bfloat16,
                       wmma::row_major> af1;
        wmma::load_matrix_sync(af0, abase + k * 16, ALD);
        wmma::load_matrix_sync(af1, abase + 16 * ALD + k * 16, ALD);
        wmma::fragment<wmma::matrix_b, 16, 16, 16, __nv_bfloat16,
                       wmma::row_major> bf0;
        wmma::fragment<wmma::matrix_b, 16, 16, 16, __nv_bfloat16,
                       wmma::row_major> bf1;
        wmma::load_matrix_sync(bf0, bbase + (k * 16) * WLD, WLD);
        wmma::load_matrix_sync(bf1, bbase + (k * 16) * WLD + 16, WLD);
        wmma::mma_sync(acc[0][0], af0, bf0, acc[0][0]);
        wmma::mma_sync(acc[0][1], af0, bf1, acc[0][1]);
        wmma::mma_sync(acc[1][0], af1, bf0, acc[1][0]);
        wmma::mma_sync(acc[1][1], af1, bf1, acc[1][1]);
    }

    __syncthreads();   // Ws/As dead; cs aliases them
    #pragma unroll
    for (int mt = 0; mt < 2; mt++) {
        #pragma unroll
        for (int nt = 0; nt < 2; nt++)
            wmma::store_matrix_sync(
                cs + (wg * 32 + mt * 16) * CLD + wi * 32 + nt * 16,
                acc[mt][nt], CLD, wmma::mem_row_major);
    }
    if (tid < 64) rowsq[tid] = 0.0f;
    __syncthreads();

    int r = tid >> 2;
    int c0 = (tid & 3) * 32;
    float vals[32];
    float sq = 0.0f;
    for (int c = 0; c < 32; c++) {
        float v = cs[r * CLD + c0 + c] + bias[c0 + c];
        v = fmaxf(v, 0.0f);
        vals[c] = v;
        sq += v * v;
    }
    atomicAdd(&rowsq[r], sq);
    __syncthreads();

    int rowg = blk0 + r;
    float* pout;
    __nv_bfloat16* phout;
    if (rowg < N) {
        pout = g_p1 + (size_t)rowg * MI;
        phout = g_p1h + (size_t)rowg * MI;
    } else {
        pout = g_p2 + (size_t)(rowg - N) * MI;
        phout = g_p2h + (size_t)(rowg - N) * MI;
    }
    float s = rsqrtf(rowsq[r]);
    for (int c = 0; c < 32; c++) {
        float o = vals[c] * s;
        pout[c0 + c] = o;
        phout[c0 + c] = __float2bfloat16_rn(o);
    }
}

// ============ sim kernel (bf16 wmma, persistent row band) ===================
// Grid (16, 128): CTA owns row band i0 (128 rows, A resident in smem) and
// loops over 8 j-tiles of 128 cols. Row sums accumulate in REGISTERS across
// tiles (one shuffle-reduce + global atomic at the end); col sums per tile.
// 256 threads = 8 warps (4M x 2N); warp tile 32x64.
// Register epilogue (accumulator lane mapping verified by Round-7 probe):
//   x[e] -> row = (lane>>2) + ((e>>1)&1)*8
//           col = (lane&3)*2 + (e&1) + ((e>>2)&1)*8
#define SLD 136            // A/B smem row stride in bf16 elements
#define SIM_SMEM (2*128*SLD*2)   // 69632 bytes
#define JTILES 8

__global__ void __launch_bounds__(256, 2) sim_kernel() {
    extern __shared__ unsigned char dynsm[];
    __nv_bfloat16* As = (__nv_bfloat16*)dynsm;
    __nv_bfloat16* Bs = As + 128 * SLD;
    __shared__ float colred[128];

    int tid = threadIdx.x;
    int warp = tid >> 5;
    int lane = tid & 31;
    int wm = warp >> 1;          // 0..3  (rows wm*32)
    int wn = warp & 1;           // 0..1  (cols wn*64)
    int i0 = blockIdx.y * 128;
    int jbase = blockIdx.x * (JTILES * 128);

    // load A once (row band resident for all 8 j-tiles)
    const uint4* srcA = (const uint4*)(g_p1h + (size_t)i0 * MI);
    for (int idx = tid; idx < 2048; idx += 256) {
        int r = idx >> 4;
        int ch = idx & 15;
        *(uint4*)(As + r * SLD + ch * 8) = srcA[idx];
    }

    const __nv_bfloat16* abase = As + (wm * 32) * SLD;
    const __nv_bfloat16* bbase = Bs + (wn * 64) * SLD;

    // loop-carried row partial sums (per lane; reduced once at the end)
    float rowacc[4];
    #pragma unroll
    for (int q = 0; q < 4; q++) rowacc[q] = 0.0f;

    for (int jt = 0; jt < JTILES; jt++) {
        int j0 = jbase + jt * 128;
        __syncthreads();   // prior tile's colred reads + B reads complete
        const uint4* srcB = (const uint4*)(g_p2h + (size_t)j0 * MI);
        for (int idx = tid; idx < 2048; idx += 256) {
            int r = idx >> 4;
            int ch = idx & 15;
            *(uint4*)(Bs + r * SLD + ch * 8) = srcB[idx];
        }
        if (tid < 128) colred[tid] = 0.0f;
        __syncthreads();

        wmma::fragment<wmma::accumulator, 16, 16, 16, float> acc[2][4];
        #pragma unroll
        for (int mt = 0; mt < 2; mt++) {
            #pragma unroll
            for (int nt = 0; nt < 4; nt++)
                wmma::fill_fragment(acc[mt][nt], 0.0f);
        }

        #pragma unroll
        for (int k = 0; k < 8; k++) {
            wmma::fragment<wmma::matrix_a, 16, 16, 16, __nv_bfloat16,
                           wmma::row_major> af0;
            wmma::fragment<wmma::matrix_a, 16, 16, 16, __nv_bfloat16,
                           wmma::row_major> af1;
            wmma::load_matrix_sync(af0, abase + k * 16, SLD);
            wmma::load_matrix_sync(af1, abase + 16 * SLD + k * 16, SLD);
            #pragma unroll
            for (int nt = 0; nt < 4; nt++) {
                wmma::fragment<wmma::matrix_b, 16, 16, 16, __nv_bfloat16,
                               wmma::col_major> bf;
                wmma::load_matrix_sync(bf, bbase + nt * 16 * SLD + k * 16,
                                       SLD);
                wmma::mma_sync(acc[0][nt], af0, bf, acc[0][nt]);
                wmma::mma_sync(acc[1][nt], af1, bf, acc[1][nt]);
            }
        }

        // exp + accumulate row partials in registers; col sums via shuffles
        float cs0[4];
        float cs1[4];
        float cs2[4];
        float cs3[4];
        #pragma unroll
        for (int nt = 0; nt < 4; nt++) {
            cs0[nt] = 0.0f;
            cs1[nt] = 0.0f;
            cs2[nt] = 0.0f;
            cs3[nt] = 0.0f;
        }
        #pragma unroll
        for (int mt = 0; mt < 2; mt++) {
            float rlo = 0.0f;
            float rhi = 0.0f;
            #pragma unroll
            for (int nt = 0; nt < 4; nt++) {
                float e0 = __expf(2.0f * acc[mt][nt].x[0]);
                float e1 = __expf(2.0f * acc[mt][nt].x[1]);
                float e2 = __expf(2.0f * acc[mt][nt].x[2]);
                float e3 = __expf(2.0f * acc[mt][nt].x[3]);
                float e4 = __expf(2.0f * acc[mt][nt].x[4]);
                float e5 = __expf(2.0f * acc[mt][nt].x[5]);
                float e6 = __expf(2.0f * acc[mt][nt].x[6]);
                float e7 = __expf(2.0f * acc[mt][nt].x[7]);
                rlo += e0 + e1 + e4 + e5;
                rhi += e2 + e3 + e6 + e7;
                cs0[nt] += e0 + e2;
                cs1[nt] += e1 + e3;
                cs2[nt] += e4 + e6;
                cs3[nt] += e5 + e7;
            }
            rowacc[mt * 2] += rlo;
            rowacc[mt * 2 + 1] += rhi;
        }
        #pragma unroll
        for (int nt = 0; nt < 4; nt++) {
            float v0 = cs0[nt];
            float v1 = cs1[nt];
            float v2 = cs2[nt];
            float v3 = cs3[nt];
            v0 += __shfl_xor_sync(0xffffffffu, v0, 4);
            v0 += __shfl_xor_sync(0xffffffffu, v0, 8);
            v0 += __shfl_xor_sync(0xffffffffu, v0, 16);
            v1 += __shfl_xor_sync(0xffffffffu, v1, 4);
            v1 += __shfl_xor_sync(0xffffffffu, v1, 8);
            v1 += __shfl_xor_sync(0xffffffffu, v1, 16);
            v2 += __shfl_xor_sync(0xffffffffu, v2, 4);
            v2 += __shfl_xor_sync(0xffffffffu, v2, 8);
            v2 += __shfl_xor_sync(0xffffffffu, v2, 16);
            v3 += __shfl_xor_sync(0xffffffffu, v3, 4);
            v3 += __shfl_xor_sync(0xffffffffu, v3, 8);
            v3 += __shfl_xor_sync(0xffffffffu, v3, 16);
            if (lane < 4) {
                int cb = wn * 64 + nt * 16 + lane * 2;
                atomicAdd(&colred[cb], v0);
                atomicAdd(&colred[cb + 1], v1);
                atomicAdd(&colred[cb + 8], v2);
                atomicAdd(&colred[cb + 9], v3);
            }
        }
        __syncthreads();
        if (tid < 128)
            atomicAdd(&g_stats[RS2 + j0 + tid], colred[tid]);
    }

    // final row reduction (once per CTA): 4 lanes share each row
    #pragma unroll
    for (int mt = 0; mt < 2; mt++) {
        float rlo = rowacc[mt * 2];
        float rhi = rowacc[mt * 2 + 1];
        rlo += __shfl_xor_sync(0xffffffffu, rlo, 1);
        rlo += __shfl_xor_sync(0xffffffffu, rlo, 2);
        rhi += __shfl_xor_sync(0xffffffffu, rhi, 1);
        rhi += __shfl_xor_sync(0xffffffffu, rhi, 2);
        if ((lane & 3) == 0) {
            int r = i0 + wm * 32 + mt * 16 + (lane >> 2);
            atomicAdd(&g_stats[RS1 + r], rlo);
            atomicAdd(&g_stats[RS1 + r + 8], rhi);
        }
    }
}

// ---------------- positives: warp per edge, both directions (fp32) ---------
__global__ void pos_kernel(const int* __restrict__ pr, const int* __restrict__ pc) {
    int e = (blockIdx.x * blockDim.x + threadIdx.x) >> 5;
    int lane = threadIdx.x & 31;
    if (e >= NEDGE) return;
    int r = pr[e];
    int c = pc[e];
    const float4* p1r = (const float4*)(g_p1 + (size_t)r * MI);
    const float4* p2r = (const float4*)(g_p2 + (size_t)r * MI);
    const float4* p1c = (const float4*)(g_p1 + (size_t)c * MI);
    const float4* p2c = (const float4*)(g_p2 + (size_t)c * MI);
    float4 a1 = p1r[lane];
    float4 b2 = p2c[lane];
    float4 a2 = p2r[lane];
    float4 b1 = p1c[lane];
    float d1 = a1.x * b2.x + a1.y * b2.y + a1.z * b2.z + a1.w * b2.w;
    float d2 = a2.x * b1.x + a2.y * b1.y + a2.z * b1.z + a2.w * b1.w;
    for (int o = 16; o > 0; o >>= 1) {
        d1 += __shfl_down_sync(0xffffffffu, d1, o);
        d2 += __shfl_down_sync(0xffffffffu, d2, o);
    }
    if (lane == 0) {
        float s1 = 2.0f * d1;
        float s2 = 2.0f * d2;
        atomicAdd(&g_stats[SP1 + r], s1);
        atomicAdd(&g_stats[PS1 + r], __expf(s1));
        atomicAdd(&g_stats[SP2 + r], s2);
        atomicAdd(&g_stats[PS2 + r], __expf(s2));
    }
}

// ---------------- loss: stage 1 over 16 blocks, stage 2 tiny ---------------
__global__ void loss_part_kernel() {
    float acc = 0.f;
    const float invcnt = 0.25f;
    int base = blockIdx.x * 1024;
    for (int it = 0; it < 4; it++) {
        int i = base + it * 256 + threadIdx.x;
        float per1 = g_stats[SP1 + i] * invcnt
                   - __logf(g_stats[RS1 + i] - g_stats[PS1 + i]);
        float per2 = g_stats[SP2 + i] * invcnt
                   - __logf(g_stats[RS2 + i] - g_stats[PS2 + i]);
        acc += per1 + per2;
    }
    __shared__ float red[8];
    for (int o = 16; o > 0; o >>= 1)
        acc += __shfl_down_sync(0xffffffffu, acc, o);
    if ((threadIdx.x & 31) == 0) red[threadIdx.x >> 5] = acc;
    __syncthreads();
    if (threadIdx.x == 0) {
        float t = 0.f;
        for (int w = 0; w < 8; w++) t += red[w];
        g_part[blockIdx.x] = t;
    }
}

__global__ void loss_final_kernel(float* out) {
    if (threadIdx.x == 0) {
        float t = 0.f;
        for (int b = 0; b < 16; b++) t += g_part[b];
        out[0] = -0.5f * t / (float)N;
    }
}

// ---------------- launch ----------------
extern "C" void kernel_launch(void* const* d_in, const int* in_sizes, int n_in,
                              void* d_out, int out_size) {
    const float* h1 = (const float*)d_in[0];
    const float* h2 = (const float*)d_in[1];
    const float* W  = (const float*)d_in[2];
    const float* b  = (const float*)d_in[3];
    const int*   pr = (const int*)d_in[4];
    const int*   pc = (const int*)d_in[5];
    float* out = (float*)d_out;

    cudaFuncSetAttribute(proj_kernel,
                         cudaFuncAttributeMaxDynamicSharedMemorySize, PJ_SMEM);
    proj_kernel<<<(2 * N) / 64, 256, PJ_SMEM>>>(h1, h2, W, b);

    pos_kernel<<<(NEDGE * 32) / 256, 256>>>(pr, pc);

    cudaFuncSetAttribute(sim_kernel,
                         cudaFuncAttributeMaxDynamicSharedMemorySize, SIM_SMEM);
    dim3 simgrid(N / (JTILES * 128), N / 128);
    sim_kernel<<<simgrid, 256, SIM_SMEM>>>();

    loss_part_kernel<<<16, 256>>>();
    loss_final_kernel<<<1, 32>>>(out);
}

// round 17
// speedup vs baseline: 2.4428x; 1.0245x over previous
#include <cuda_runtime.h>
#include <cuda_bf16.h>
#include <cuda_pipeline.h>
#include <mma.h>
#include <math.h>

using namespace nvcuda;

#define N 16384
#define HID 256
#define MI 128
#define NEDGE (N*4)

// stats layout inside g_stats
#define RS1 0
#define RS2 (N)
#define PS1 (2*N)
#define PS2 (3*N)
#define SP1 (4*N)
#define SP2 (5*N)

// ---------------- scratch (device globals; no allocation allowed) ----------
__device__ float g_p1[(size_t)N*MI];
__device__ float g_p2[(size_t)N*MI];
__device__ __nv_bfloat16 g_p1h[(size_t)N*MI];
__device__ __nv_bfloat16 g_p2h[(size_t)N*MI];
__device__ float g_stats[6*N];
__device__ float g_part[16];

// ============ projection (bf16 wmma, smem-staged): p = l2norm(relu(hW+b)) ===
// CTA: 64 rows x 128 cols, 256 threads = 8 warps (2 row groups x 4 col quads).
// Full W staged bf16 in smem once per CTA. Grid 512; each block zeroes 192
// floats of g_stats (512*192 = 6*N).
#define WLD 136   // Ws row stride (bf16)
#define ALD 264   // As row stride (bf16)
#define CLD 132   // epilogue staging stride (float)
#define PJ_SMEM (256*WLD*2 + 64*ALD*2)   // 103424 bytes

__global__ void __launch_bounds__(256, 1) proj_kernel(
        const float* __restrict__ h1, const float* __restrict__ h2,
        const float* __restrict__ W, const float* __restrict__ bias) {
    extern __shared__ unsigned char pj_sm[];
    __nv_bfloat16* Ws = (__nv_bfloat16*)pj_sm;
    __nv_bfloat16* As = Ws + 256 * WLD;
    float* cs = (float*)pj_sm;          // aliases Ws/As after mainloop
    __shared__ float rowsq[64];

    int tid = threadIdx.x;
    int warp = tid >> 5;
    int wg = warp >> 2;          // 0..1 -> rows wg*32
    int wi = warp & 3;           // 0..3 -> cols wi*32
    int blk0 = blockIdx.x * 64;

    if (tid < 192) g_stats[blockIdx.x * 192 + tid] = 0.0f;

    const float* hsrc;
    if (blk0 < N) hsrc = h1 + (size_t)blk0 * HID;
    else          hsrc = h2 + (size_t)(blk0 - N) * HID;

    for (int idx = tid; idx < 8192; idx += 256) {
        int k = idx >> 5;
        int n4 = (idx & 31) * 4;
        float4 v = *(const float4*)(W + (size_t)k * MI + n4);
        __nv_bfloat162 lo;
        lo.x = __float2bfloat16_rn(v.x);
        lo.y = __float2bfloat16_rn(v.y);
        __nv_bfloat162 hi;
        hi.x = __float2bfloat16_rn(v.z);
        hi.y = __float2bfloat16_rn(v.w);
        *(__nv_bfloat162*)(Ws + k * WLD + n4) = lo;
        *(__nv_bfloat162*)(Ws + k * WLD + n4 + 2) = hi;
    }
    for (int idx = tid; idx < 4096; idx += 256) {
        int r = idx >> 6;
        int c4 = (idx & 63) * 4;
        float4 v = *(const float4*)(hsrc + (size_t)r * HID + c4);
        __nv_bfloat162 lo;
        lo.x = __float2bfloat16_rn(v.x);
        lo.y = __float2bfloat16_rn(v.y);
        __nv_bfloat162 hi;
        hi.x = __float2bfloat16_rn(v.z);
        hi.y = __float2bfloat16_rn(v.w);
        *(__nv_bfloat162*)(As + r * ALD + c4) = lo;
        *(__nv_bfloat162*)(As + r * ALD + c4 + 2) = hi;
    }
    __syncthreads();

    wmma::fragment<wmma::accumulator, 16, 16, 16, float> acc[2][2];
    #pragma unroll
    for (int mt = 0; mt < 2; mt++) {
        #pragma unroll
        for (int nt = 0; nt < 2; nt++)
            wmma::fill_fragment(acc[mt][nt], 0.0f);
    }

    const __nv_bfloat16* abase = As + (wg * 32) * ALD;
    const __nv_bfloat16* bbase = Ws + wi * 32;

    #pragma unroll
    for (int k = 0; k < 16; k++) {
        wmma::fragment<wmma::matrix_a, 16, 16, 16, __nv_bfloat16,
                       wmma::row_major> af0;
        wmma::fragment<wmma::matrix_a, 16, 16, 16, __nv_bfloat16,
                       wmma::row_major> af1;
        wmma::load_matrix_sync(af0, abase + k * 16, ALD);
        wmma::load_matrix_sync(af1, abase + 16 * ALD + k * 16, ALD);
        wmma::fragment<wmma::matrix_b, 16, 16, 16, __nv_bfloat16,
                       wmma::row_major> bf0;
        wmma::fragment<wmma::matrix_b, 16, 16, 16, __nv_bfloat16,
                       wmma::row_major> bf1;
        wmma::load_matrix_sync(bf0, bbase + (k * 16) * WLD, WLD);
        wmma::load_matrix_sync(bf1, bbase + (k * 16) * WLD + 16, WLD);
        wmma::mma_sync(acc[0][0], af0, bf0, acc[0][0]);
        wmma::mma_sync(acc[0][1], af0, bf1, acc[0][1]);
        wmma::mma_sync(acc[1][0], af1, bf0, acc[1][0]);
        wmma::mma_sync(acc[1][1], af1, bf1, acc[1][1]);
    }

    __syncthreads();   // Ws/As dead; cs aliases them
    #pragma unroll
    for (int mt = 0; mt < 2; mt++) {
        #pragma unroll
        for (int nt = 0; nt < 2; nt++)
            wmma::store_matrix_sync(
                cs + (wg * 32 + mt * 16) * CLD + wi * 32 + nt * 16,
                acc[mt][nt], CLD, wmma::mem_row_major);
    }
    if (tid < 64) rowsq[tid] = 0.0f;
    __syncthreads();

    int r = tid >> 2;
    int c0 = (tid & 3) * 32;
    float vals[32];
    float sq = 0.0f;
    for (int c = 0; c < 32; c++) {
        float v = cs[r * CLD + c0 + c] + bias[c0 + c];
        v = fmaxf(v, 0.0f);
        vals[c] = v;
        sq += v * v;
    }
    atomicAdd(&rowsq[r], sq);
    __syncthreads();

    int rowg = blk0 + r;
    float* pout;
    __nv_bfloat16* phout;
    if (rowg < N) {
        pout = g_p1 + (size_t)rowg * MI;
        phout = g_p1h + (size_t)rowg * MI;
    } else {
        pout = g_p2 + (size_t)(rowg - N) * MI;
        phout = g_p2h + (size_t)(rowg - N) * MI;
    }
    float s = rsqrtf(rowsq[r]);
    for (int c = 0; c < 32; c++) {
        float o = vals[c] * s;
        pout[c0 + c] = o;
        phout[c0 + c] = __float2bfloat16_rn(o);
    }
}

// ============ sim kernel (bf16 wmma, persistent row band, async B) ==========
// Grid (16, 128): CTA owns a 128-row band (A resident) and loops 8 j-tiles.
// B tiles are DOUBLE-BUFFERED via __pipeline_memcpy_async so the next tile's
// global->smem copy overlaps the current tile's HMMA+exp. Row sums carried in
// registers across tiles. 256 threads = 8 warps (4M x 2N); warp tile 32x64.
// Register epilogue (accumulator lane mapping verified by Round-7 probe):
//   x[e] -> row = (lane>>2) + ((e>>1)&1)*8
//           col = (lane&3)*2 + (e&1) + ((e>>2)&1)*8
#define SLD 136            // A/B smem row stride in bf16 elements
#define BTILE (128*SLD)    // bf16 elements per B buffer
#define SIM_SMEM (3*128*SLD*2)   // A + 2xB = 104448 bytes
#define JTILES 8

__global__ void __launch_bounds__(256, 2) sim_kernel() {
    extern __shared__ unsigned char dynsm[];
    __nv_bfloat16* As = (__nv_bfloat16*)dynsm;
    __nv_bfloat16* Bs0 = As + BTILE;
    __nv_bfloat16* Bs1 = Bs0 + BTILE;
    __shared__ float colred[128];

    int tid = threadIdx.x;
    int warp = tid >> 5;
    int lane = tid & 31;
    int wm = warp >> 1;          // 0..3  (rows wm*32)
    int wn = warp & 1;           // 0..1  (cols wn*64)
    int i0 = blockIdx.y * 128;
    int jbase = blockIdx.x * (JTILES * 128);

    // kick off async copy of B tile 0 into Bs0
    {
        const uint4* srcB = (const uint4*)(g_p2h + (size_t)jbase * MI);
        for (int idx = tid; idx < 2048; idx += 256) {
            int r = idx >> 4;
            int ch = idx & 15;
            __pipeline_memcpy_async(Bs0 + r * SLD + ch * 8, srcB + idx, 16);
        }
        __pipeline_commit();
    }

    // load A once (row band resident for all 8 j-tiles)
    const uint4* srcA = (const uint4*)(g_p1h + (size_t)i0 * MI);
    for (int idx = tid; idx < 2048; idx += 256) {
        int r = idx >> 4;
        int ch = idx & 15;
        *(uint4*)(As + r * SLD + ch * 8) = srcA[idx];
    }

    const __nv_bfloat16* abase = As + (wm * 32) * SLD;

    float rowacc[4];
    #pragma unroll
    for (int q = 0; q < 4; q++) rowacc[q] = 0.0f;

    for (int jt = 0; jt < JTILES; jt++) {
        int j0 = jbase + jt * 128;
        __nv_bfloat16* Bcur = (jt & 1) ? Bs1 : Bs0;
        __nv_bfloat16* Bnxt = (jt & 1) ? Bs0 : Bs1;

        // issue next tile's copy (buffer Bnxt was fully consumed in jt-1,
        // whose trailing __syncthreads has already passed)
        if (jt + 1 < JTILES) {
            const uint4* srcB =
                (const uint4*)(g_p2h + (size_t)(j0 + 128) * MI);
            for (int idx = tid; idx < 2048; idx += 256) {
                int r = idx >> 4;
                int ch = idx & 15;
                __pipeline_memcpy_async(Bnxt + r * SLD + ch * 8, srcB + idx,
                                        16);
            }
            __pipeline_commit();
            __pipeline_wait_prior(1);   // tile jt's copy complete
        } else {
            __pipeline_wait_prior(0);
        }
        if (tid < 128) colred[tid] = 0.0f;
        __syncthreads();   // all threads' tile-jt data visible

        const __nv_bfloat16* bbase = Bcur + (wn * 64) * SLD;

        wmma::fragment<wmma::accumulator, 16, 16, 16, float> acc[2][4];
        #pragma unroll
        for (int mt = 0; mt < 2; mt++) {
            #pragma unroll
            for (int nt = 0; nt < 4; nt++)
                wmma::fill_fragment(acc[mt][nt], 0.0f);
        }

        #pragma unroll
        for (int k = 0; k < 8; k++) {
            wmma::fragment<wmma::matrix_a, 16, 16, 16, __nv_bfloat16,
                           wmma::row_major> af0;
            wmma::fragment<wmma::matrix_a, 16, 16, 16, __nv_bfloat16,
                           wmma::row_major> af1;
            wmma::load_matrix_sync(af0, abase + k * 16, SLD);
            wmma::load_matrix_sync(af1, abase + 16 * SLD + k * 16, SLD);
            #pragma unroll
            for (int nt = 0; nt < 4; nt++) {
                wmma::fragment<wmma::matrix_b, 16, 16, 16, __nv_bfloat16,
                               wmma::col_major> bf;
                wmma::load_matrix_sync(bf, bbase + nt * 16 * SLD + k * 16,
                                       SLD);
                wmma::mma_sync(acc[0][nt], af0, bf, acc[0][nt]);
                wmma::mma_sync(acc[1][nt], af1, bf, acc[1][nt]);
            }
        }

        float cs0[4];
        float cs1[4];
        float cs2[4];
        float cs3[4];
        #pragma unroll
        for (int nt = 0; nt < 4; nt++) {
            cs0[nt] = 0.0f;
            cs1[nt] = 0.0f;
            cs2[nt] = 0.0f;
            cs3[nt] = 0.0f;
        }
        #pragma unroll
        for (int mt = 0; mt < 2; mt++) {
            float rlo = 0.0f;
            float rhi = 0.0f;
            #pragma unroll
            for (int nt = 0; nt < 4; nt++) {
                float e0 = __expf(2.0f * acc[mt][nt].x[0]);
                float e1 = __expf(2.0f * acc[mt][nt].x[1]);
                float e2 = __expf(2.0f * acc[mt][nt].x[2]);
                float e3 = __expf(2.0f * acc[mt][nt].x[3]);
                float e4 = __expf(2.0f * acc[mt][nt].x[4]);
                float e5 = __expf(2.0f * acc[mt][nt].x[5]);
                float e6 = __expf(2.0f * acc[mt][nt].x[6]);
                float e7 = __expf(2.0f * acc[mt][nt].x[7]);
                rlo += e0 + e1 + e4 + e5;
                rhi += e2 + e3 + e6 + e7;
                cs0[nt] += e0 + e2;
                cs1[nt] += e1 + e3;
                cs2[nt] += e4 + e6;
                cs3[nt] += e5 + e7;
            }
            rowacc[mt * 2] += rlo;
            rowacc[mt * 2 + 1] += rhi;
        }
        #pragma unroll
        for (int nt = 0; nt < 4; nt++) {
            float v0 = cs0[nt];
            float v1 = cs1[nt];
            float v2 = cs2[nt];
            float v3 = cs3[nt];
            v0 += __shfl_xor_sync(0xffffffffu, v0, 4);
            v0 += __shfl_xor_sync(0xffffffffu, v0, 8);
            v0 += __shfl_xor_sync(0xffffffffu, v0, 16);
            v1 += __shfl_xor_sync(0xffffffffu, v1, 4);
            v1 += __shfl_xor_sync(0xffffffffu, v1, 8);
            v1 += __shfl_xor_sync(0xffffffffu, v1, 16);
            v2 += __shfl_xor_sync(0xffffffffu, v2, 4);
            v2 += __shfl_xor_sync(0xffffffffu, v2, 8);
            v2 += __shfl_xor_sync(0xffffffffu, v2, 16);
            v3 += __shfl_xor_sync(0xffffffffu, v3, 4);
            v3 += __shfl_xor_sync(0xffffffffu, v3, 8);
            v3 += __shfl_xor_sync(0xffffffffu, v3, 16);
            if (lane < 4) {
                int cb = wn * 64 + nt * 16 + lane * 2;
                atomicAdd(&colred[cb], v0);
                atomicAdd(&colred[cb + 1], v1);
                atomicAdd(&colred[cb + 8], v2);
                atomicAdd(&colred[cb + 9], v3);
            }
        }
        __syncthreads();
        if (tid < 128)
            atomicAdd(&g_stats[RS2 + j0 + tid], colred[tid]);
    }

    // final row reduction (once per CTA): 4 lanes share each row
    #pragma unroll
    for (int mt = 0; mt < 2; mt++) {
        float rlo = rowacc[mt * 2];
        float rhi = rowacc[mt * 2 + 1];
        rlo += __shfl_xor_sync(0xffffffffu, rlo, 1);
        rlo += __shfl_xor_sync(0xffffffffu, rlo, 2);
        rhi += __shfl_xor_sync(0xffffffffu, rhi, 1);
        rhi += __shfl_xor_sync(0xffffffffu, rhi, 2);
        if ((lane & 3) == 0) {
            int r = i0 + wm * 32 + mt * 16 + (lane >> 2);
            atomicAdd(&g_stats[RS1 + r], rlo);
            atomicAdd(&g_stats[RS1 + r + 8], rhi);
        }
    }
}

// ---------------- positives: warp per edge, both directions (fp32) ---------
__global__ void pos_kernel(const int* __restrict__ pr, const int* __restrict__ pc) {
    int e = (blockIdx.x * blockDim.x + threadIdx.x) >> 5;
    int lane = threadIdx.x & 31;
    if (e >= NEDGE) return;
    int r = pr[e];
    int c = pc[e];
    const float4* p1r = (const float4*)(g_p1 + (size_t)r * MI);
    const float4* p2r = (const float4*)(g_p2 + (size_t)r * MI);
    const float4* p1c = (const float4*)(g_p1 + (size_t)c * MI);
    const float4* p2c = (const float4*)(g_p2 + (size_t)c * MI);
    float4 a1 = p1r[lane];
    float4 b2 = p2c[lane];
    float4 a2 = p2r[lane];
    float4 b1 = p1c[lane];
    float d1 = a1.x * b2.x + a1.y * b2.y + a1.z * b2.z + a1.w * b2.w;
    float d2 = a2.x * b1.x + a2.y * b1.y + a2.z * b1.z + a2.w * b1.w;
    for (int o = 16; o > 0; o >>= 1) {
        d1 += __shfl_down_sync(0xffffffffu, d1, o);
        d2 += __shfl_down_sync(0xffffffffu, d2, o);
    }
    if (lane == 0) {
        float s1 = 2.0f * d1;
        float s2 = 2.0f * d2;
        atomicAdd(&g_stats[SP1 + r], s1);
        atomicAdd(&g_stats[PS1 + r], __expf(s1));
        atomicAdd(&g_stats[SP2 + r], s2);
        atomicAdd(&g_stats[PS2 + r], __expf(s2));
    }
}

// ---------------- loss: stage 1 over 16 blocks, stage 2 tiny ---------------
__global__ void loss_part_kernel() {
    float acc = 0.f;
    const float invcnt = 0.25f;
    int base = blockIdx.x * 1024;
    for (int it = 0; it < 4; it++) {
        int i = base + it * 256 + threadIdx.x;
        float per1 = g_stats[SP1 + i] * invcnt
                   - __logf(g_stats[RS1 + i] - g_stats[PS1 + i]);
        float per2 = g_stats[SP2 + i] * invcnt
                   - __logf(g_stats[RS2 + i] - g_stats[PS2 + i]);
        acc += per1 + per2;
    }
    __shared__ float red[8];
    for (int o = 16; o > 0; o >>= 1)
        acc += __shfl_down_sync(0xffffffffu, acc, o);
    if ((threadIdx.x & 31) == 0) red[threadIdx.x >> 5] = acc;
    __syncthreads();
    if (threadIdx.x == 0) {
        float t = 0.f;
        for (int w = 0; w < 8; w++) t += red[w];
        g_part[blockIdx.x] = t;
    }
}

__global__ void loss_final_kernel(float* out) {
    if (threadIdx.x == 0) {
        float t = 0.f;
        for (int b = 0; b < 16; b++) t += g_part[b];
        out[0] = -0.5f * t / (float)N;
    }
}

// ---------------- launch ----------------
extern "C" void kernel_launch(void* const* d_in, const int* in_sizes, int n_in,
                              void* d_out, int out_size) {
    const float* h1 = (const float*)d_in[0];
    const float* h2 = (const float*)d_in[1];
    const float* W  = (const float*)d_in[2];
    const float* b  = (const float*)d_in[3];
    const int*   pr = (const int*)d_in[4];
    const int*   pc = (const int*)d_in[5];
    float* out = (float*)d_out;

    cudaFuncSetAttribute(proj_kernel,
                         cudaFuncAttributeMaxDynamicSharedMemorySize, PJ_SMEM);
    proj_kernel<<<(2 * N) / 64, 256, PJ_SMEM>>>(h1, h2, W, b);

    pos_kernel<<<(NEDGE * 32) / 256, 256>>>(pr, pc);

    cudaFuncSetAttribute(sim_kernel,
                         cudaFuncAttributeMaxDynamicSharedMemorySize, SIM_SMEM);
    dim3 simgrid(N / (JTILES * 128), N / 128);
    sim_kernel<<<simgrid, 256, SIM_SMEM>>>();

    loss_part_kernel<<<16, 256>>>();
    loss_final_kernel<<<1, 32>>>(out);
}